// round 12
// baseline (speedup 1.0000x reference)
#include <cuda_runtime.h>
#include <math.h>

#define EPS 1e-12f
typedef unsigned long long ull;

// ---- packed f32x2 helpers (each half = separately-rounded IEEE op) ---------
__device__ __forceinline__ ull pack2(float lo, float hi) {
    ull r; asm("mov.b64 %0, {%1,%2};" : "=l"(r) : "f"(lo), "f"(hi)); return r;
}
__device__ __forceinline__ void unpack2(ull p, float& lo, float& hi) {
    asm("mov.b64 {%0,%1}, %2;" : "=f"(lo), "=f"(hi) : "l"(p));
}
__device__ __forceinline__ ull ffma2(ull a, ull b, ull c) {
    ull d; asm("fma.rn.f32x2 %0, %1, %2, %3;" : "=l"(d) : "l"(a), "l"(b), "l"(c));
    return d;
}

// ---------------- persistent scratch ----------------------------------------
__device__ ull    g_wn1p[40 * 75];    // conv1 weights, channel-pair packed
__device__ float  g_e1[80];
__device__ float  g_wn2d[80 * 9];
__device__ float  g_e2d[80];
__device__ ull    g_wn2pp[20 * 80];   // pointwise weights, channel-pair packed
__device__ float  g_e2p[40];
__device__ float  g_wn3T[40 * 9 * 40]; // layer3 weights, [co][kk][cin] c-fastest
__device__ float  g_e3[40];
__device__ float  g_qv[4];

__device__ float g_xn1[1024 * 784];           // layer1 patch-norm denominators
__device__ float g_buf1[1024 * 80 * 14 * 14]; // pooled layer1 g-output
__device__ float g_buf2[1024 * 40 * 6 * 6];   // pooled layer2 g-output

// g(y) = sign(y) * (|y|+EPS)^e
__device__ __forceinline__ float scs_g(float y, float e) {
    float a = __fadd_rn(fabsf(y), EPS);
    float r = powf(a, e);
    return (y > 0.f) ? r : ((y < 0.f) ? -r : 0.f);
}

__device__ __forceinline__ float maxabs4(float a, float b, float c, float d) {
    float pmx = fmaxf(fmaxf(a, b), fmaxf(c, d));
    float pmn = fminf(fminf(a, b), fminf(c, d));
    return (pmx >= -pmn) ? pmx : pmn;
}

// ---------------- weight prep (chains bit-identical) ------------------------
__global__ void prep_kernel(const float* w1, const float* p1, const float* q1,
                            const float* w2d, const float* p2d, const float* q2d,
                            const float* w2p, const float* p2p, const float* q2p,
                            const float* w3, const float* p3, const float* q3) {
    int b = blockIdx.x, t = threadIdx.x;
    const float *w, *p, *q;
    float *wn, *e;
    int n, c, li;
    if (b < 80)       { c = b;       w = w1  + c * 75;  n = 75;  wn = 0;              p = p1;  q = q1;  e = g_e1;  li = 0; }
    else if (b < 160) { c = b - 80;  w = w2d + c * 9;   n = 9;   wn = g_wn2d + c * 9; p = p2d; q = q2d; e = g_e2d; li = 1; }
    else if (b < 200) { c = b - 160; w = w2p + c * 80;  n = 80;  wn = 0;              p = p2p; q = q2p; e = g_e2p; li = 2; }
    else              { c = b - 200; w = w3  + c * 360; n = 360; wn = 0;              p = p3;  q = q3;  e = g_e3;  li = 3; }
    float qt = __fdiv_rn(q[0], 100.0f);
    float qv = __fmul_rn(qt, qt);
    float s = 0.f;
    for (int i = t; i < n; i += 32) {
        float v = w[i];
        s = __fadd_rn(s, __fmul_rn(v, v));
    }
    #pragma unroll
    for (int o = 16; o > 0; o >>= 1)
        s = __fadd_rn(s, __shfl_down_sync(0xffffffffu, s, o));
    s = __shfl_sync(0xffffffffu, s, 0);
    float wnorm = __fadd_rn(sqrtf(__fadd_rn(s, EPS)), qv);
    for (int i = t; i < n; i += 32) {
        float v = __fdiv_rn(w[i], wnorm);
        if (li == 0) {
            ((float*)g_wn1p)[(c >> 1) * 150 + 2 * i + (c & 1)] = v;
        } else if (li == 2) {
            ((float*)g_wn2pp)[(c >> 1) * 160 + 2 * i + (c & 1)] = v;
        } else if (li == 3) {
            int kk = i % 9, cin = i / 9;
            g_wn3T[(c * 9 + kk) * 40 + cin] = v;
        } else {
            wn[i] = v;
        }
    }
    if (t == 0) {
        float pe = __fdiv_rn(p[c], 10.0f);
        e[c] = __fmul_rn(pe, pe);
        if (c == 0) g_qv[li] = qv;
    }
}

// ---------------- layer1 patch norms ((ky,kx,c) order) ----------------------
__global__ void xnorm1_kernel(const float* x) {
    __shared__ float sx[3072];
    int img = blockIdx.x;
    const float* xp = x + img * 3072;
    for (int i = threadIdx.x; i < 3072; i += 256) sx[i] = xp[i];
    __syncthreads();
    float qv = g_qv[0];
    for (int pos = threadIdx.x; pos < 784; pos += 256) {
        int oy = pos / 28, ox = pos % 28;
        float ss = 0.f;
        #pragma unroll
        for (int ky = 0; ky < 5; ky++)
            #pragma unroll
            for (int kx = 0; kx < 5; kx++)
                #pragma unroll
                for (int c = 0; c < 3; c++) {
                    float v = sx[c * 1024 + (oy + ky) * 32 + ox + kx];
                    ss = __fadd_rn(ss, __fmul_rn(v, v));
                }
        g_xn1[img * 784 + pos] = __fadd_rn(sqrtf(__fadd_rn(ss, EPS)), qv);
    }
}

// ---------------- layer1: conv 5x5 + pool + g, channel-pair FFMA2 -----------
__global__ void __launch_bounds__(196, 3) conv1_kernel(const float* x) {
    __shared__ float sx[3072];
    __shared__ ull   sw2[300];
    __shared__ float sxn[784];
    __shared__ float se[8];
    int img = blockIdx.x;
    int cb = blockIdx.y * 8;
    int tid = threadIdx.x;
    const float* xp = x + img * 3072;
    const ull* wsrc = g_wn1p + (cb >> 1) * 75;
    for (int i = tid; i < 3072; i += 196) sx[i] = xp[i];
    if (tid < 150) { sw2[tid] = wsrc[tid]; sw2[tid + 150] = wsrc[tid + 150]; }
    for (int i = tid; i < 784; i += 196) sxn[i] = g_xn1[img * 784 + i];
    if (tid < 8) se[tid] = g_e1[cb + tid];
    __syncthreads();

    int ct = tid / 98, pp = tid % 98;
    int py = pp / 7;
    int pq = pp % 7;
    int cx0 = 4 * pq;

    ull acc2[2][8];
    #pragma unroll
    for (int a = 0; a < 2; a++)
        #pragma unroll
        for (int j = 0; j < 8; j++) acc2[a][j] = 0ull;

    #pragma unroll 1
    for (int c = 0; c < 3; c++) {
        float xw[6][8];
        #pragma unroll
        for (int i = 0; i < 6; i++)
            #pragma unroll
            for (int j = 0; j < 8; j++)
                xw[i][j] = sx[c * 1024 + (2 * py + i) * 32 + cx0 + j];
        #pragma unroll
        for (int ky = 0; ky < 5; ky++)
            #pragma unroll
            for (int kx = 0; kx < 5; kx++) {
                ull xp2[8];
                #pragma unroll
                for (int r = 0; r < 2; r++)
                    #pragma unroll
                    for (int cl = 0; cl < 4; cl++) {
                        float v = xw[ky + r][kx + cl];
                        xp2[r * 4 + cl] = pack2(v, v);
                    }
                int widx = c * 25 + ky * 5 + kx;
                #pragma unroll
                for (int t2 = 0; t2 < 2; t2++) {
                    ull w2 = sw2[(ct * 2 + t2) * 75 + widx];
                    #pragma unroll
                    for (int j = 0; j < 8; j++)
                        acc2[t2][j] = ffma2(w2, xp2[j], acc2[t2][j]);
                }
            }
    }

    float xnv[8];
    #pragma unroll
    for (int r = 0; r < 2; r++)
        #pragma unroll
        for (int cl = 0; cl < 4; cl++)
            xnv[r * 4 + cl] = sxn[(2 * py + r) * 28 + cx0 + cl];

    #pragma unroll
    for (int t2 = 0; t2 < 2; t2++) {
        float ya[8], yb[8];
        #pragma unroll
        for (int j = 0; j < 8; j++) unpack2(acc2[t2][j], ya[j], yb[j]);
        #pragma unroll
        for (int j = 0; j < 8; j++) {
            ya[j] = __fdiv_rn(ya[j], xnv[j]);
            yb[j] = __fdiv_rn(yb[j], xnv[j]);
        }
        int co = cb + ct * 4 + 2 * t2;
        float e0 = se[ct * 4 + 2 * t2];
        float e1 = se[ct * 4 + 2 * t2 + 1];
        int o0 = ((img * 80 + co) * 14 + py) * 14 + 2 * pq;
        int o1 = o0 + 196;
        g_buf1[o0]     = scs_g(maxabs4(ya[0], ya[1], ya[4], ya[5]), e0);
        g_buf1[o0 + 1] = scs_g(maxabs4(ya[2], ya[3], ya[6], ya[7]), e0);
        g_buf1[o1]     = scs_g(maxabs4(yb[0], yb[1], yb[4], yb[5]), e1);
        g_buf1[o1 + 1] = scs_g(maxabs4(yb[2], yb[3], yb[6], yb[7]), e1);
    }
}

// ---------------- layer2 merged: depthwise + pointwise + pool + g -----------
__global__ void __launch_bounds__(768, 2) k2_kernel() {
    extern __shared__ char smc[];
    float* s_t2d = (float*)smc;                       // 11520 f = 46080 B
    ull*   s_w2  = (ull*)(smc + 46080);               // 1600 ull = 12800 B
    float* s_xn  = (float*)(smc + 46080 + 12800);     // 144 f
    float* s_e2p = s_xn + 144;                        // 40 f
    int img = blockIdx.x, tid = threadIdx.x;

    for (int i = tid; i < 1600; i += 768) s_w2[i] = g_wn2pp[i];
    if (tid < 40) s_e2p[tid] = g_e2p[tid];
    float qv2d = g_qv[1], qv2p = g_qv[2];

    // phase A: depthwise 3x3 + g -> smem; half-row tiles (chains unchanged)
    for (int tile = tid; tile < 1920; tile += 768) {
        int ch = tile / 24, rest = tile % 24;
        int oy = rest / 2, half = rest % 2;
        int ox0 = half * 6;
        const float* wp = g_wn2d + ch * 9;
        float wreg[9];
        #pragma unroll
        for (int k = 0; k < 9; k++) wreg[k] = wp[k];
        float e = g_e2d[ch];
        const float* xr = g_buf1 + (img * 80 + ch) * 196 + oy * 14 + ox0;
        float rw[3][8];
        #pragma unroll
        for (int rr = 0; rr < 3; rr++)
            #pragma unroll
            for (int j = 0; j < 8; j++) rw[rr][j] = __ldg(&xr[rr * 14 + j]);
        float* op = s_t2d + ch * 144 + oy * 12 + ox0;
        #pragma unroll
        for (int ox = 0; ox < 6; ox++) {
            float num = 0.f, ss = 0.f;
            #pragma unroll
            for (int ky = 0; ky < 3; ky++)
                #pragma unroll
                for (int kx = 0; kx < 3; kx++) {
                    float v = rw[ky][ox + kx];
                    num = fmaf(wreg[ky * 3 + kx], v, num);
                    ss  = __fadd_rn(ss, __fmul_rn(v, v));
                }
            float y = __fdiv_rn(num, __fadd_rn(sqrtf(__fadd_rn(ss, EPS)), qv2d));
            op[ox] = scs_g(y, e);
        }
    }
    __syncthreads();

    // phase B1: per-pixel channel-norm denominators (k-sequential)
    if (tid < 144) {
        int pix = tid;
        float ss = 0.f;
        for (int k = 0; k < 80; k++) {
            float v = s_t2d[k * 144 + pix];
            ss = __fadd_rn(ss, __fmul_rn(v, v));
        }
        s_xn[pix] = __fadd_rn(sqrtf(__fadd_rn(ss, EPS)), qv2p);
    }
    __syncthreads();

    // phase B2: pointwise, one channel-pair per thread + pool 2x2 + g
    if (tid < 720) {
        int cop = tid / 36, quad = tid % 36;   // co pair = (2cop, 2cop+1)
        int qy = quad / 6, qx = quad % 6;
        int p00 = (2 * qy) * 12 + 2 * qx;
        int p01 = p00 + 1, p10 = p00 + 12, p11 = p00 + 13;
        ull a0 = 0ull, a1 = 0ull, a2 = 0ull, a3 = 0ull;
        for (int k = 0; k < 80; k++) {
            float x0 = s_t2d[k * 144 + p00], x1 = s_t2d[k * 144 + p01];
            float x2 = s_t2d[k * 144 + p10], x3 = s_t2d[k * 144 + p11];
            ull w2 = s_w2[cop * 80 + k];
            a0 = ffma2(w2, pack2(x0, x0), a0);
            a1 = ffma2(w2, pack2(x1, x1), a1);
            a2 = ffma2(w2, pack2(x2, x2), a2);
            a3 = ffma2(w2, pack2(x3, x3), a3);
        }
        float n0 = s_xn[p00], n1 = s_xn[p01], n2 = s_xn[p10], n3 = s_xn[p11];
        float u0, v0, u1, v1, u2, v2, u3, v3;
        unpack2(a0, u0, v0); unpack2(a1, u1, v1);
        unpack2(a2, u2, v2); unpack2(a3, u3, v3);
        float va = maxabs4(__fdiv_rn(u0, n0), __fdiv_rn(u1, n1),
                           __fdiv_rn(u2, n2), __fdiv_rn(u3, n3));
        float vb = maxabs4(__fdiv_rn(v0, n0), __fdiv_rn(v1, n1),
                           __fdiv_rn(v2, n2), __fdiv_rn(v3, n3));
        int co0 = 2 * cop, co1 = co0 + 1;
        g_buf2[((img * 40 + co0) * 6 + qy) * 6 + qx] = scs_g(va, s_e2p[co0]);
        g_buf2[((img * 40 + co1) * 6 + qy) * 6 + qx] = scs_g(vb, s_e2p[co1]);
    }
}

// ---------------- layer3: 4 images/block, transposed smem, FFMA2 ------------
#define L3_IN_STRIDE 44
#define L3_IMG_F 1600
__global__ void __launch_bounds__(640, 2) layer3_kernel(const float* wo, const float* bo,
                                                        float* out, int N) {
    extern __shared__ float sm[];
    float* s_w3   = sm;                    // 14400  [co][kk][cin]
    float* s_wo   = s_w3 + 14400;          // 400
    float* s_bo   = s_wo + 400;            // 16
    float* s_e3   = s_bo + 16;             // 40
    float* s_inT  = s_e3 + 40 + 8;         // 4 * 1600  [img][pos*44+c]
    float* s_xn   = s_inT + 4 * L3_IMG_F;  // 4 * 16
    float* s_qmax = s_xn + 64;             // 4 * 160
    float* s_qmin = s_qmax + 640;          // 4 * 160
    float* s_vec  = s_qmin + 640;          // 4 * 40
    int tid = threadIdx.x;
    int img0 = blockIdx.x * 4;
    int limg = tid / 160, ltid = tid % 160;

    for (int i = tid; i < 3600; i += 640)
        ((float4*)s_w3)[i] = ((const float4*)g_wn3T)[i];
    for (int i = tid; i < 400; i += 640) s_wo[i] = wo[i];
    if (tid < 40) s_e3[tid] = g_e3[tid];
    if (tid < 10) s_bo[tid] = bo[tid];
    for (int i = tid; i < 4 * 1440; i += 640) {
        int il = i / 1440, r = i % 1440;
        int c = r / 36, pos = r % 36;
        s_inT[il * L3_IMG_F + pos * L3_IN_STRIDE + c] = g_buf2[(img0 + il) * 1440 + r];
    }
    __syncthreads();
    float qv3 = g_qv[3];
    const float* inT = s_inT + limg * L3_IMG_F;

    if (ltid < 16) {   // patch norms: (ky,kx,c) order, c ascending via float4
        int oy = ltid / 4, ox = ltid % 4;
        float ss = 0.f;
        #pragma unroll
        for (int ky = 0; ky < 3; ky++)
            #pragma unroll
            for (int kx = 0; kx < 3; kx++) {
                const float* ip = &inT[((oy + ky) * 6 + ox + kx) * L3_IN_STRIDE];
                #pragma unroll
                for (int c4 = 0; c4 < 40; c4 += 4) {
                    float4 v = *(const float4*)(ip + c4);
                    ss = __fadd_rn(ss, __fmul_rn(v.x, v.x));
                    ss = __fadd_rn(ss, __fmul_rn(v.y, v.y));
                    ss = __fadd_rn(ss, __fmul_rn(v.z, v.z));
                    ss = __fadd_rn(ss, __fmul_rn(v.w, v.w));
                }
            }
        s_xn[limg * 16 + ltid] = __fadd_rn(sqrtf(__fadd_rn(ss, EPS)), qv3);
    }

    {   // conv (ky,kx,c ascending): thread = (out-ch, 2x2 quad); FFMA2 pairs
        int co = ltid >> 2, quad = ltid & 3;
        int qy = quad >> 1, qx = quad & 1;
        ull accA = 0ull, accB = 0ull;   // (pos0,pos1), (pos2,pos3)
        #pragma unroll
        for (int ky = 0; ky < 3; ky++)
            #pragma unroll
            for (int kx = 0; kx < 3; kx++) {
                const float* wp = &s_w3[(co * 9 + ky * 3 + kx) * 40];
                const float* i0 = &inT[((2 * qy + ky) * 6 + 2 * qx + kx) * L3_IN_STRIDE];
                const float* i1 = i0 + L3_IN_STRIDE;
                const float* i2 = &inT[((2 * qy + 1 + ky) * 6 + 2 * qx + kx) * L3_IN_STRIDE];
                const float* i3 = i2 + L3_IN_STRIDE;
                #pragma unroll
                for (int c4 = 0; c4 < 40; c4 += 4) {
                    float4 w = *(const float4*)(wp + c4);
                    float4 v0 = *(const float4*)(i0 + c4);
                    float4 v1 = *(const float4*)(i1 + c4);
                    float4 v2 = *(const float4*)(i2 + c4);
                    float4 v3 = *(const float4*)(i3 + c4);
                    accA = ffma2(pack2(w.x, w.x), pack2(v0.x, v1.x), accA);
                    accB = ffma2(pack2(w.x, w.x), pack2(v2.x, v3.x), accB);
                    accA = ffma2(pack2(w.y, w.y), pack2(v0.y, v1.y), accA);
                    accB = ffma2(pack2(w.y, w.y), pack2(v2.y, v3.y), accB);
                    accA = ffma2(pack2(w.z, w.z), pack2(v0.z, v1.z), accA);
                    accB = ffma2(pack2(w.z, w.z), pack2(v2.z, v3.z), accB);
                    accA = ffma2(pack2(w.w, w.w), pack2(v0.w, v1.w), accA);
                    accB = ffma2(pack2(w.w, w.w), pack2(v2.w, v3.w), accB);
                }
            }
        __syncthreads();   // s_xn ready (also separates norm/conv phases)
        float a0, a1, a2, a3;
        unpack2(accA, a0, a1);
        unpack2(accB, a2, a3);
        const float* xn = &s_xn[limg * 16];
        float y0 = __fdiv_rn(a0, xn[(2 * qy) * 4 + 2 * qx]);
        float y1 = __fdiv_rn(a1, xn[(2 * qy) * 4 + 2 * qx + 1]);
        float y2 = __fdiv_rn(a2, xn[(2 * qy + 1) * 4 + 2 * qx]);
        float y3 = __fdiv_rn(a3, xn[(2 * qy + 1) * 4 + 2 * qx + 1]);
        s_qmax[limg * 160 + ltid] = fmaxf(fmaxf(y0, y1), fmaxf(y2, y3));
        s_qmin[limg * 160 + ltid] = fminf(fminf(y0, y1), fminf(y2, y3));
    }
    __syncthreads();
    if (ltid < 40) {
        const float* qmx = &s_qmax[limg * 160 + ltid * 4];
        const float* qmn = &s_qmin[limg * 160 + ltid * 4];
        float pmx = fmaxf(fmaxf(qmx[0], qmx[1]), fmaxf(qmx[2], qmx[3]));
        float pmn = fminf(fminf(qmn[0], qmn[1]), fminf(qmn[2], qmn[3]));
        float v = (pmx >= -pmn) ? pmx : pmn;
        s_vec[limg * 40 + ltid] = scs_g(v, s_e3[ltid]);
    }
    __syncthreads();
    if (ltid < 10) {
        float s = 0.f;
        const float* tv = &s_vec[limg * 40];
        #pragma unroll 1
        for (int c = 0; c < 40; c++) s = fmaf(tv[c], s_wo[ltid * 40 + c], s);
        out[(img0 + limg) * 10 + ltid] = __fadd_rn(s, s_bo[ltid]);
    }
}

// ---------------- launch ------------------------------------------------------
extern "C" void kernel_launch(void* const* d_in, const int* in_sizes, int n_in,
                              void* d_out, int out_size) {
    const float* x   = (const float*)d_in[0];
    const float* w1  = (const float*)d_in[1];
    const float* p1  = (const float*)d_in[2];
    const float* q1  = (const float*)d_in[3];
    const float* w2d = (const float*)d_in[4];
    const float* p2d = (const float*)d_in[5];
    const float* q2d = (const float*)d_in[6];
    const float* w2p = (const float*)d_in[7];
    const float* p2p = (const float*)d_in[8];
    const float* q2p = (const float*)d_in[9];
    const float* w3  = (const float*)d_in[10];
    const float* p3  = (const float*)d_in[11];
    const float* q3  = (const float*)d_in[12];
    const float* wo  = (const float*)d_in[13];
    const float* bo  = (const float*)d_in[14];
    float* out = (float*)d_out;

    int N = in_sizes[0] / 3072;

    static const size_t SM2 = 46080 + 12800 + 144 * 4 + 40 * 4 + 64;
    static const size_t SM3 = (14400 + 400 + 16 + 40 + 8 + 4 * L3_IMG_F
                               + 64 + 640 + 640 + 160 + 16) * sizeof(float);
    cudaFuncSetAttribute(k2_kernel, cudaFuncAttributeMaxDynamicSharedMemorySize, (int)SM2);
    cudaFuncSetAttribute(layer3_kernel, cudaFuncAttributeMaxDynamicSharedMemorySize, (int)SM3);

    prep_kernel<<<240, 32>>>(w1, p1, q1, w2d, p2d, q2d, w2p, p2p, q2p, w3, p3, q3);
    xnorm1_kernel<<<N, 256>>>(x);
    conv1_kernel<<<dim3(N, 10), 196>>>(x);
    k2_kernel<<<N, 768, SM2>>>();
    layer3_kernel<<<N / 4, 640, SM3>>>(wo, bo, out, N);
}

// round 13
// speedup vs baseline: 1.3308x; 1.3308x over previous
#include <cuda_runtime.h>
#include <math.h>

#define EPS 1e-12f
typedef unsigned long long ull;

// ---- packed f32x2 helpers (each half = separately-rounded IEEE op) ---------
__device__ __forceinline__ ull pack2(float lo, float hi) {
    ull r; asm("mov.b64 %0, {%1,%2};" : "=l"(r) : "f"(lo), "f"(hi)); return r;
}
__device__ __forceinline__ void unpack2(ull p, float& lo, float& hi) {
    asm("mov.b64 {%0,%1}, %2;" : "=f"(lo), "=f"(hi) : "l"(p));
}
__device__ __forceinline__ ull ffma2(ull a, ull b, ull c) {
    ull d; asm("fma.rn.f32x2 %0, %1, %2, %3;" : "=l"(d) : "l"(a), "l"(b), "l"(c));
    return d;
}

// ---------------- persistent scratch ----------------------------------------
__device__ ull    g_wn1p[40 * 75];    // conv1 weights, channel-pair packed
__device__ float  g_e1[80];
__device__ float  g_wn2d[80 * 9];
__device__ float  g_e2d[80];
__device__ ull    g_wn2pp[20 * 80];   // pointwise weights, channel-pair packed
__device__ float  g_e2p[40];
__device__ float  g_wn3[40 * 360];
__device__ float  g_e3[40];
__device__ float  g_qv[4];

__device__ float g_xn1[1024 * 784];           // layer1 patch-norm denominators
__device__ float g_buf1[1024 * 80 * 14 * 14]; // pooled layer1 g-output
__device__ float g_buf2[1024 * 40 * 6 * 6];   // pooled layer2 g-output

// g(y) = sign(y) * (|y|+EPS)^e
__device__ __forceinline__ float scs_g(float y, float e) {
    float a = __fadd_rn(fabsf(y), EPS);
    float r = powf(a, e);
    return (y > 0.f) ? r : ((y < 0.f) ? -r : 0.f);
}

__device__ __forceinline__ float maxabs4(float a, float b, float c, float d) {
    float pmx = fmaxf(fmaxf(a, b), fmaxf(c, d));
    float pmn = fminf(fminf(a, b), fminf(c, d));
    return (pmx >= -pmn) ? pmx : pmn;
}

// ---------------- weight prep (chains bit-identical) ------------------------
__global__ void prep_kernel(const float* w1, const float* p1, const float* q1,
                            const float* w2d, const float* p2d, const float* q2d,
                            const float* w2p, const float* p2p, const float* q2p,
                            const float* w3, const float* p3, const float* q3) {
    int b = blockIdx.x, t = threadIdx.x;
    const float *w, *p, *q;
    float *wn, *e;
    int n, c, li;
    if (b < 80)       { c = b;       w = w1  + c * 75;  n = 75;  wn = 0;              p = p1;  q = q1;  e = g_e1;  li = 0; }
    else if (b < 160) { c = b - 80;  w = w2d + c * 9;   n = 9;   wn = g_wn2d + c * 9; p = p2d; q = q2d; e = g_e2d; li = 1; }
    else if (b < 200) { c = b - 160; w = w2p + c * 80;  n = 80;  wn = 0;              p = p2p; q = q2p; e = g_e2p; li = 2; }
    else              { c = b - 200; w = w3  + c * 360; n = 360; wn = g_wn3 + c * 360; p = p3; q = q3;  e = g_e3;  li = 3; }
    float qt = __fdiv_rn(q[0], 100.0f);
    float qv = __fmul_rn(qt, qt);
    float s = 0.f;
    for (int i = t; i < n; i += 32) {
        float v = w[i];
        s = __fadd_rn(s, __fmul_rn(v, v));
    }
    #pragma unroll
    for (int o = 16; o > 0; o >>= 1)
        s = __fadd_rn(s, __shfl_down_sync(0xffffffffu, s, o));
    s = __shfl_sync(0xffffffffu, s, 0);
    float wnorm = __fadd_rn(sqrtf(__fadd_rn(s, EPS)), qv);
    for (int i = t; i < n; i += 32) {
        float v = __fdiv_rn(w[i], wnorm);
        if (li == 0) {
            ((float*)g_wn1p)[(c >> 1) * 150 + 2 * i + (c & 1)] = v;
        } else if (li == 2) {
            ((float*)g_wn2pp)[(c >> 1) * 160 + 2 * i + (c & 1)] = v;
        } else {
            wn[i] = v;
        }
    }
    if (t == 0) {
        float pe = __fdiv_rn(p[c], 10.0f);
        e[c] = __fmul_rn(pe, pe);
        if (c == 0) g_qv[li] = qv;
    }
}

// ---------------- layer1 patch norms ((ky,kx,c) order) ----------------------
__global__ void xnorm1_kernel(const float* x) {
    __shared__ float sx[3072];
    int img = blockIdx.x;
    const float* xp = x + img * 3072;
    for (int i = threadIdx.x; i < 3072; i += 256) sx[i] = xp[i];
    __syncthreads();
    float qv = g_qv[0];
    for (int pos = threadIdx.x; pos < 784; pos += 256) {
        int oy = pos / 28, ox = pos % 28;
        float ss = 0.f;
        #pragma unroll
        for (int ky = 0; ky < 5; ky++)
            #pragma unroll
            for (int kx = 0; kx < 5; kx++)
                #pragma unroll
                for (int c = 0; c < 3; c++) {
                    float v = sx[c * 1024 + (oy + ky) * 32 + ox + kx];
                    ss = __fadd_rn(ss, __fmul_rn(v, v));
                }
        g_xn1[img * 784 + pos] = __fadd_rn(sqrtf(__fadd_rn(ss, EPS)), qv);
    }
}

// ---------------- layer1: conv 5x5 + pool + g, channel-pair FFMA2 -----------
// rolling 2-row packed x buffer: packs hoisted out of (ky,kx); chains keep the
// exact (c,ky,kx) fmaf order per output.
__global__ void __launch_bounds__(196, 3) conv1_kernel(const float* x) {
    __shared__ float sx[3072];
    __shared__ ull   sw2[300];
    __shared__ float sxn[784];
    __shared__ float se[8];
    int img = blockIdx.x;
    int cb = blockIdx.y * 8;
    int tid = threadIdx.x;
    const float* xp = x + img * 3072;
    const ull* wsrc = g_wn1p + (cb >> 1) * 75;
    for (int i = tid; i < 3072; i += 196) sx[i] = xp[i];
    if (tid < 150) { sw2[tid] = wsrc[tid]; sw2[tid + 150] = wsrc[tid + 150]; }
    for (int i = tid; i < 784; i += 196) sxn[i] = g_xn1[img * 784 + i];
    if (tid < 8) se[tid] = g_e1[cb + tid];
    __syncthreads();

    int ct = tid / 98, pp = tid % 98;
    int py = pp / 7;
    int pq = pp % 7;
    int cx0 = 4 * pq;

    ull acc2[2][8];
    #pragma unroll
    for (int a = 0; a < 2; a++)
        #pragma unroll
        for (int j = 0; j < 8; j++) acc2[a][j] = 0ull;

    #pragma unroll 1
    for (int c = 0; c < 3; c++) {
        const float* xbase = &sx[c * 1024 + (2 * py) * 32 + cx0];
        ull xdA[8], xdB[8];
        #pragma unroll
        for (int j = 0; j < 8; j++) { float v = xbase[j];      xdA[j] = pack2(v, v); }
        #pragma unroll
        for (int j = 0; j < 8; j++) { float v = xbase[32 + j]; xdB[j] = pack2(v, v); }
        #pragma unroll
        for (int ky = 0; ky < 5; ky++) {
            #pragma unroll
            for (int kx = 0; kx < 5; kx++) {
                int widx = c * 25 + ky * 5 + kx;
                #pragma unroll
                for (int t2 = 0; t2 < 2; t2++) {
                    ull w2 = sw2[(ct * 2 + t2) * 75 + widx];
                    #pragma unroll
                    for (int cl = 0; cl < 4; cl++) {
                        acc2[t2][cl]     = ffma2(w2, xdA[kx + cl], acc2[t2][cl]);
                        acc2[t2][4 + cl] = ffma2(w2, xdB[kx + cl], acc2[t2][4 + cl]);
                    }
                }
            }
            if (ky < 4) {   // rotate rows (fully unrolled -> register renaming)
                #pragma unroll
                for (int j = 0; j < 8; j++) xdA[j] = xdB[j];
                #pragma unroll
                for (int j = 0; j < 8; j++) {
                    float v = xbase[(ky + 2) * 32 + j];
                    xdB[j] = pack2(v, v);
                }
            }
        }
    }

    float xnv[8];
    #pragma unroll
    for (int r = 0; r < 2; r++)
        #pragma unroll
        for (int cl = 0; cl < 4; cl++)
            xnv[r * 4 + cl] = sxn[(2 * py + r) * 28 + cx0 + cl];

    #pragma unroll
    for (int t2 = 0; t2 < 2; t2++) {
        float ya[8], yb[8];
        #pragma unroll
        for (int j = 0; j < 8; j++) unpack2(acc2[t2][j], ya[j], yb[j]);
        #pragma unroll
        for (int j = 0; j < 8; j++) {
            ya[j] = __fdiv_rn(ya[j], xnv[j]);
            yb[j] = __fdiv_rn(yb[j], xnv[j]);
        }
        int co = cb + ct * 4 + 2 * t2;
        float e0 = se[ct * 4 + 2 * t2];
        float e1 = se[ct * 4 + 2 * t2 + 1];
        int o0 = ((img * 80 + co) * 14 + py) * 14 + 2 * pq;
        int o1 = o0 + 196;
        g_buf1[o0]     = scs_g(maxabs4(ya[0], ya[1], ya[4], ya[5]), e0);
        g_buf1[o0 + 1] = scs_g(maxabs4(ya[2], ya[3], ya[6], ya[7]), e0);
        g_buf1[o1]     = scs_g(maxabs4(yb[0], yb[1], yb[4], yb[5]), e1);
        g_buf1[o1 + 1] = scs_g(maxabs4(yb[2], yb[3], yb[6], yb[7]), e1);
    }
}

// ---------------- layer2 merged: depthwise + pointwise + pool + g -----------
__global__ void __launch_bounds__(384, 3) k2_kernel() {
    extern __shared__ char smc[];
    float* s_t2d = (float*)smc;                       // 11520 f = 46080 B
    ull*   s_w2  = (ull*)(smc + 46080);               // 1600 ull = 12800 B
    float* s_xn  = (float*)(smc + 46080 + 12800);     // 144 f
    float* s_e2p = s_xn + 144;                        // 40 f
    int img = blockIdx.x, tid = threadIdx.x;

    for (int i = tid; i < 1600; i += 384) s_w2[i] = g_wn2pp[i];
    if (tid < 40) s_e2p[tid] = g_e2p[tid];
    float qv2d = g_qv[1], qv2p = g_qv[2];

    // phase A: depthwise 3x3 + g -> smem; half-row tiles (chains unchanged)
    for (int tile = tid; tile < 1920; tile += 384) {
        int ch = tile / 24, rest = tile % 24;
        int oy = rest / 2, half = rest % 2;
        int ox0 = half * 6;
        const float* wp = g_wn2d + ch * 9;
        float wreg[9];
        #pragma unroll
        for (int k = 0; k < 9; k++) wreg[k] = wp[k];
        float e = g_e2d[ch];
        const float* xr = g_buf1 + (img * 80 + ch) * 196 + oy * 14 + ox0;
        float rw[3][8];
        #pragma unroll
        for (int rr = 0; rr < 3; rr++)
            #pragma unroll
            for (int j = 0; j < 8; j++) rw[rr][j] = __ldg(&xr[rr * 14 + j]);
        float* op = s_t2d + ch * 144 + oy * 12 + ox0;
        #pragma unroll
        for (int ox = 0; ox < 6; ox++) {
            float num = 0.f, ss = 0.f;
            #pragma unroll
            for (int ky = 0; ky < 3; ky++)
                #pragma unroll
                for (int kx = 0; kx < 3; kx++) {
                    float v = rw[ky][ox + kx];
                    num = fmaf(wreg[ky * 3 + kx], v, num);
                    ss  = __fadd_rn(ss, __fmul_rn(v, v));
                }
            float y = __fdiv_rn(num, __fadd_rn(sqrtf(__fadd_rn(ss, EPS)), qv2d));
            op[ox] = scs_g(y, e);
        }
    }
    __syncthreads();

    // phase B1: per-pixel channel-norm denominators, pixel-pair float2 loads
    if (tid < 72) {
        int pix0 = 2 * tid;
        float ssa = 0.f, ssb = 0.f;
        for (int k = 0; k < 80; k++) {
            float2 v = *(const float2*)&s_t2d[k * 144 + pix0];
            ssa = __fadd_rn(ssa, __fmul_rn(v.x, v.x));
            ssb = __fadd_rn(ssb, __fmul_rn(v.y, v.y));
        }
        s_xn[pix0]     = __fadd_rn(sqrtf(__fadd_rn(ssa, EPS)), qv2p);
        s_xn[pix0 + 1] = __fadd_rn(sqrtf(__fadd_rn(ssb, EPS)), qv2p);
    }
    __syncthreads();

    // phase B2: pointwise, channel-pair FFMA2 + pool 2x2 + g (float2 x loads)
    if (tid < 360) {
        int cg = tid / 36, quad = tid % 36;   // cg covers pairs 2cg, 2cg+1
        int qy = quad / 6, qx = quad % 6;
        int p00 = (2 * qy) * 12 + 2 * qx;
        int p10 = p00 + 12;
        ull acc2[2][4];
        #pragma unroll
        for (int pr = 0; pr < 2; pr++)
            #pragma unroll
            for (int j = 0; j < 4; j++) acc2[pr][j] = 0ull;
        for (int k = 0; k < 80; k++) {
            float2 xa = *(const float2*)&s_t2d[k * 144 + p00];   // x0, x1
            float2 xb = *(const float2*)&s_t2d[k * 144 + p10];   // x2, x3
            ull xv0 = pack2(xa.x, xa.x), xv1 = pack2(xa.y, xa.y);
            ull xv2 = pack2(xb.x, xb.x), xv3 = pack2(xb.y, xb.y);
            #pragma unroll
            for (int pr = 0; pr < 2; pr++) {
                ull w2 = s_w2[(cg * 2 + pr) * 80 + k];
                acc2[pr][0] = ffma2(w2, xv0, acc2[pr][0]);
                acc2[pr][1] = ffma2(w2, xv1, acc2[pr][1]);
                acc2[pr][2] = ffma2(w2, xv2, acc2[pr][2]);
                acc2[pr][3] = ffma2(w2, xv3, acc2[pr][3]);
            }
        }
        float n0 = s_xn[p00], n1 = s_xn[p00 + 1], n2 = s_xn[p10], n3 = s_xn[p10 + 1];
        #pragma unroll
        for (int pr = 0; pr < 2; pr++) {
            float a0, b0, a1, b1, a2, b2, a3, b3;
            unpack2(acc2[pr][0], a0, b0);
            unpack2(acc2[pr][1], a1, b1);
            unpack2(acc2[pr][2], a2, b2);
            unpack2(acc2[pr][3], a3, b3);
            float va = maxabs4(__fdiv_rn(a0, n0), __fdiv_rn(a1, n1),
                               __fdiv_rn(a2, n2), __fdiv_rn(a3, n3));
            float vb = maxabs4(__fdiv_rn(b0, n0), __fdiv_rn(b1, n1),
                               __fdiv_rn(b2, n2), __fdiv_rn(b3, n3));
            int co0 = cg * 4 + 2 * pr;
            int co1 = co0 + 1;
            g_buf2[((img * 40 + co0) * 6 + qy) * 6 + qx] = scs_g(va, s_e2p[co0]);
            g_buf2[((img * 40 + co1) * 6 + qy) * 6 + qx] = scs_g(vb, s_e2p[co1]);
        }
    }
}

// ---------------- layer3: conv 3x3 (FFMA2) + pool 4x4 + g + FC --------------
__global__ void __launch_bounds__(160) layer3_kernel(const float* wo, const float* bo, float* out) {
    extern __shared__ float sm[];
    float* s_in   = sm;              // 1440
    float* s_w3   = sm + 1440;       // 14400
    float* s_wo   = s_w3 + 14400;    // 400
    float* s_e3   = s_wo + 400;      // 40
    float* s_xn   = s_e3 + 40;       // 16
    float* s_qmax = s_xn + 16;       // 160
    float* s_qmin = s_qmax + 160;    // 160
    float* s_vec  = s_qmin + 160;    // 40
    float* s_bo   = s_vec + 40;      // 16
    int img = blockIdx.x, tid = threadIdx.x;

    const float4* src = (const float4*)(g_buf2 + img * 1440);
    for (int i = tid; i < 360; i += 160) ((float4*)s_in)[i] = src[i];
    for (int i = tid; i < 3600; i += 160) ((float4*)s_w3)[i] = ((const float4*)g_wn3)[i];
    for (int i = tid; i < 400; i += 160) s_wo[i] = wo[i];
    if (tid < 40) s_e3[tid] = g_e3[tid];
    if (tid < 10) s_bo[tid] = bo[tid];
    __syncthreads();
    float qv3 = g_qv[3];

    if (tid < 16) {
        int oy = tid / 4, ox = tid % 4;
        float ss = 0.f;
        #pragma unroll
        for (int ky = 0; ky < 3; ky++)
            #pragma unroll
            for (int kx = 0; kx < 3; kx++)
                for (int c = 0; c < 40; c++) {
                    float v = s_in[c * 36 + (oy + ky) * 6 + ox + kx];
                    ss = __fadd_rn(ss, __fmul_rn(v, v));
                }
        s_xn[tid] = __fadd_rn(sqrtf(__fadd_rn(ss, EPS)), qv3);
    }
    __syncthreads();

    {   // conv with FFMA2 position pairs (halves keep their exact chains)
        int co = tid >> 2, quad = tid & 3;
        int qy = quad >> 1, qx = quad & 1;
        ull accA = 0ull, accB = 0ull;
        #pragma unroll
        for (int ky = 0; ky < 3; ky++)
            #pragma unroll
            for (int kx = 0; kx < 3; kx++)
                for (int c = 0; c < 40; c++) {
                    float w = s_w3[(co * 40 + c) * 9 + ky * 3 + kx];
                    ull w2 = pack2(w, w);
                    const float* ip = &s_in[c * 36];
                    float v0 = ip[(2 * qy + ky) * 6 + 2 * qx + kx];
                    float v1 = ip[(2 * qy + ky) * 6 + 2 * qx + 1 + kx];
                    float v2 = ip[(2 * qy + 1 + ky) * 6 + 2 * qx + kx];
                    float v3 = ip[(2 * qy + 1 + ky) * 6 + 2 * qx + 1 + kx];
                    accA = ffma2(w2, pack2(v0, v1), accA);
                    accB = ffma2(w2, pack2(v2, v3), accB);
                }
        float a0, a1, a2, a3;
        unpack2(accA, a0, a1);
        unpack2(accB, a2, a3);
        float y0 = __fdiv_rn(a0, s_xn[(2 * qy) * 4 + 2 * qx]);
        float y1 = __fdiv_rn(a1, s_xn[(2 * qy) * 4 + 2 * qx + 1]);
        float y2 = __fdiv_rn(a2, s_xn[(2 * qy + 1) * 4 + 2 * qx]);
        float y3 = __fdiv_rn(a3, s_xn[(2 * qy + 1) * 4 + 2 * qx + 1]);
        s_qmax[tid] = fmaxf(fmaxf(y0, y1), fmaxf(y2, y3));
        s_qmin[tid] = fminf(fminf(y0, y1), fminf(y2, y3));
    }
    __syncthreads();
    if (tid < 40) {
        float pmx = fmaxf(fmaxf(s_qmax[tid * 4], s_qmax[tid * 4 + 1]),
                          fmaxf(s_qmax[tid * 4 + 2], s_qmax[tid * 4 + 3]));
        float pmn = fminf(fminf(s_qmin[tid * 4], s_qmin[tid * 4 + 1]),
                          fminf(s_qmin[tid * 4 + 2], s_qmin[tid * 4 + 3]));
        float v = (pmx >= -pmn) ? pmx : pmn;
        s_vec[tid] = scs_g(v, s_e3[tid]);
    }
    __syncthreads();
    if (tid < 10) {
        float s = 0.f;
        #pragma unroll 1
        for (int c = 0; c < 40; c++) s = fmaf(s_vec[c], s_wo[tid * 40 + c], s);
        out[img * 10 + tid] = __fadd_rn(s, s_bo[tid]);
    }
}

// ---------------- launch ------------------------------------------------------
extern "C" void kernel_launch(void* const* d_in, const int* in_sizes, int n_in,
                              void* d_out, int out_size) {
    const float* x   = (const float*)d_in[0];
    const float* w1  = (const float*)d_in[1];
    const float* p1  = (const float*)d_in[2];
    const float* q1  = (const float*)d_in[3];
    const float* w2d = (const float*)d_in[4];
    const float* p2d = (const float*)d_in[5];
    const float* q2d = (const float*)d_in[6];
    const float* w2p = (const float*)d_in[7];
    const float* p2p = (const float*)d_in[8];
    const float* q2p = (const float*)d_in[9];
    const float* w3  = (const float*)d_in[10];
    const float* p3  = (const float*)d_in[11];
    const float* q3  = (const float*)d_in[12];
    const float* wo  = (const float*)d_in[13];
    const float* bo  = (const float*)d_in[14];
    float* out = (float*)d_out;

    int N = in_sizes[0] / 3072;

    static const size_t SM2 = 46080 + 12800 + 144 * 4 + 40 * 4 + 64;
    static const size_t SM3 = (1440 + 14400 + 400 + 40 + 16 + 160 + 160 + 40 + 16) * sizeof(float);
    cudaFuncSetAttribute(k2_kernel, cudaFuncAttributeMaxDynamicSharedMemorySize, (int)SM2);
    cudaFuncSetAttribute(layer3_kernel, cudaFuncAttributeMaxDynamicSharedMemorySize, (int)SM3);

    prep_kernel<<<240, 32>>>(w1, p1, q1, w2d, p2d, q2d, w2p, p2p, q2p, w3, p3, q3);
    xnorm1_kernel<<<N, 256>>>(x);
    conv1_kernel<<<dim3(N, 10), 196>>>(x);
    k2_kernel<<<N, 384, SM2>>>();
    layer3_kernel<<<N, 160, SM3>>>(wo, bo, out);
}

// round 14
// speedup vs baseline: 1.4883x; 1.1184x over previous
#include <cuda_runtime.h>
#include <math.h>

#define EPS 1e-12f
typedef unsigned long long ull;

// ---- packed f32x2 helpers (each half = separately-rounded IEEE op) ---------
__device__ __forceinline__ ull pack2(float lo, float hi) {
    ull r; asm("mov.b64 %0, {%1,%2};" : "=l"(r) : "f"(lo), "f"(hi)); return r;
}
__device__ __forceinline__ void unpack2(ull p, float& lo, float& hi) {
    asm("mov.b64 {%0,%1}, %2;" : "=f"(lo), "=f"(hi) : "l"(p));
}
__device__ __forceinline__ ull ffma2(ull a, ull b, ull c) {
    ull d; asm("fma.rn.f32x2 %0, %1, %2, %3;" : "=l"(d) : "l"(a), "l"(b), "l"(c));
    return d;
}

// ---------------- persistent scratch ----------------------------------------
__device__ ull    g_wn1p[40 * 75];    // conv1 weights, channel-pair packed
__device__ float  g_e1[80];
__device__ float  g_wn2d[80 * 9];
__device__ float  g_e2d[80];
__device__ ull    g_wn2pp[20 * 80];   // pointwise weights, channel-pair packed
__device__ float  g_e2p[40];
__device__ float  g_wn3[40 * 360];
__device__ float  g_e3[40];
__device__ float  g_qv[4];

__device__ float g_buf1[1024 * 80 * 14 * 14]; // pooled layer1 g-output
__device__ float g_buf2[1024 * 40 * 6 * 6];   // pooled layer2 g-output

// g(y) = sign(y) * (|y|+EPS)^e
__device__ __forceinline__ float scs_g(float y, float e) {
    float a = __fadd_rn(fabsf(y), EPS);
    float r = powf(a, e);
    return (y > 0.f) ? r : ((y < 0.f) ? -r : 0.f);
}

__device__ __forceinline__ float maxabs4(float a, float b, float c, float d) {
    float pmx = fmaxf(fmaxf(a, b), fmaxf(c, d));
    float pmn = fminf(fminf(a, b), fminf(c, d));
    return (pmx >= -pmn) ? pmx : pmn;
}

// ---------------- weight prep (chains bit-identical) ------------------------
__global__ void prep_kernel(const float* w1, const float* p1, const float* q1,
                            const float* w2d, const float* p2d, const float* q2d,
                            const float* w2p, const float* p2p, const float* q2p,
                            const float* w3, const float* p3, const float* q3) {
    int b = blockIdx.x, t = threadIdx.x;
    const float *w, *p, *q;
    float *wn, *e;
    int n, c, li;
    if (b < 80)       { c = b;       w = w1  + c * 75;  n = 75;  wn = 0;              p = p1;  q = q1;  e = g_e1;  li = 0; }
    else if (b < 160) { c = b - 80;  w = w2d + c * 9;   n = 9;   wn = g_wn2d + c * 9; p = p2d; q = q2d; e = g_e2d; li = 1; }
    else if (b < 200) { c = b - 160; w = w2p + c * 80;  n = 80;  wn = 0;              p = p2p; q = q2p; e = g_e2p; li = 2; }
    else              { c = b - 200; w = w3  + c * 360; n = 360; wn = g_wn3 + c * 360; p = p3; q = q3;  e = g_e3;  li = 3; }
    float qt = __fdiv_rn(q[0], 100.0f);
    float qv = __fmul_rn(qt, qt);
    float s = 0.f;
    for (int i = t; i < n; i += 32) {
        float v = w[i];
        s = __fadd_rn(s, __fmul_rn(v, v));
    }
    #pragma unroll
    for (int o = 16; o > 0; o >>= 1)
        s = __fadd_rn(s, __shfl_down_sync(0xffffffffu, s, o));
    s = __shfl_sync(0xffffffffu, s, 0);
    float wnorm = __fadd_rn(sqrtf(__fadd_rn(s, EPS)), qv);
    for (int i = t; i < n; i += 32) {
        float v = __fdiv_rn(w[i], wnorm);
        if (li == 0) {
            ((float*)g_wn1p)[(c >> 1) * 150 + 2 * i + (c & 1)] = v;
        } else if (li == 2) {
            ((float*)g_wn2pp)[(c >> 1) * 160 + 2 * i + (c & 1)] = v;
        } else {
            wn[i] = v;
        }
    }
    if (t == 0) {
        float pe = __fdiv_rn(p[c], 10.0f);
        e[c] = __fmul_rn(pe, pe);
        if (c == 0) g_qv[li] = qv;
    }
}

// ---------------- megakernel: one image per block, all layers ---------------
// smem (floats), phase-aliased union:
//  conv : sx[3072] | sw2(ull)[3000->6000f] | sxn[784] | se[80]      = 9936
//  k2   : t2d[11520] | w2(ull)[1600->3200f] | xn2[144] | e2p[40]    = 14904
//  l3   : in[1440] | w3[14400] | wo[400] | e3[40] | xn3[16]
//         | qmax[160] | qmin[160] | vec[40] | bo[16]                = 16672
#define MEGA_SMEMF 16672
__global__ void __launch_bounds__(392, 2) mega_kernel(const float* x,
                                                      const float* wo_g, const float* bo_g,
                                                      float* out) {
    extern __shared__ float sm[];
    int img = blockIdx.x, tid = threadIdx.x;

    // ===== phase 0: load image + conv1 weights =====
    {
        float* sx = sm;
        ull*   sw2 = (ull*)(sm + 3072);
        float* se = sm + 3072 + 6000 + 784;
        const float* xp = x + img * 3072;
        for (int i = tid; i < 3072; i += 392) sx[i] = xp[i];
        for (int i = tid; i < 3000; i += 392) sw2[i] = g_wn1p[i];
        if (tid < 80) se[tid] = g_e1[tid];
    }
    __syncthreads();

    // ===== phase 1: layer1 patch norms ((ky,kx,c) chain) =====
    {
        float* sx = sm;
        float* sxn = sm + 3072 + 6000;
        float qv = g_qv[0];
        for (int pos = tid; pos < 784; pos += 392) {
            int oy = pos / 28, ox = pos % 28;
            float ss = 0.f;
            #pragma unroll
            for (int ky = 0; ky < 5; ky++)
                #pragma unroll
                for (int kx = 0; kx < 5; kx++)
                    #pragma unroll
                    for (int c = 0; c < 3; c++) {
                        float v = sx[c * 1024 + (oy + ky) * 32 + ox + kx];
                        ss = __fadd_rn(ss, __fmul_rn(v, v));
                    }
            sxn[pos] = __fadd_rn(sqrtf(__fadd_rn(ss, EPS)), qv);
        }
    }
    __syncthreads();

    // ===== phase 2: conv1 5x5 + pool + g (5 passes x 16 out-channels) =====
    {
        float* sx = sm;
        ull*   sw2 = (ull*)(sm + 3072);
        float* sxn = sm + 3072 + 6000;
        float* se = sxn + 784;
        int ct = tid / 98, pp = tid % 98;   // ct 0..3
        int py = pp / 7;
        int pq = pp % 7;
        int cx0 = 4 * pq;

        float xnv[8];
        #pragma unroll
        for (int r = 0; r < 2; r++)
            #pragma unroll
            for (int cl = 0; cl < 4; cl++)
                xnv[r * 4 + cl] = sxn[(2 * py + r) * 28 + cx0 + cl];

        #pragma unroll 1
        for (int pass = 0; pass < 5; pass++) {
            ull acc2[2][8];
            #pragma unroll
            for (int a = 0; a < 2; a++)
                #pragma unroll
                for (int j = 0; j < 8; j++) acc2[a][j] = 0ull;

            #pragma unroll 1
            for (int c = 0; c < 3; c++) {
                const float* xbase = &sx[c * 1024 + (2 * py) * 32 + cx0];
                ull xdA[8], xdB[8];
                #pragma unroll
                for (int j = 0; j < 8; j++) { float v = xbase[j];      xdA[j] = pack2(v, v); }
                #pragma unroll
                for (int j = 0; j < 8; j++) { float v = xbase[32 + j]; xdB[j] = pack2(v, v); }
                #pragma unroll
                for (int ky = 0; ky < 5; ky++) {
                    #pragma unroll
                    for (int kx = 0; kx < 5; kx++) {
                        int widx = c * 25 + ky * 5 + kx;
                        #pragma unroll
                        for (int t2 = 0; t2 < 2; t2++) {
                            ull w2 = sw2[(pass * 8 + ct * 2 + t2) * 75 + widx];
                            #pragma unroll
                            for (int cl = 0; cl < 4; cl++) {
                                acc2[t2][cl]     = ffma2(w2, xdA[kx + cl], acc2[t2][cl]);
                                acc2[t2][4 + cl] = ffma2(w2, xdB[kx + cl], acc2[t2][4 + cl]);
                            }
                        }
                    }
                    if (ky < 4) {
                        #pragma unroll
                        for (int j = 0; j < 8; j++) xdA[j] = xdB[j];
                        #pragma unroll
                        for (int j = 0; j < 8; j++) {
                            float v = xbase[(ky + 2) * 32 + j];
                            xdB[j] = pack2(v, v);
                        }
                    }
                }
            }

            #pragma unroll
            for (int t2 = 0; t2 < 2; t2++) {
                float ya[8], yb[8];
                #pragma unroll
                for (int j = 0; j < 8; j++) unpack2(acc2[t2][j], ya[j], yb[j]);
                #pragma unroll
                for (int j = 0; j < 8; j++) {
                    ya[j] = __fdiv_rn(ya[j], xnv[j]);
                    yb[j] = __fdiv_rn(yb[j], xnv[j]);
                }
                int co = pass * 16 + ct * 4 + 2 * t2;
                float e0 = se[co];
                float e1 = se[co + 1];
                int o0 = ((img * 80 + co) * 14 + py) * 14 + 2 * pq;
                int o1 = o0 + 196;
                g_buf1[o0]     = scs_g(maxabs4(ya[0], ya[1], ya[4], ya[5]), e0);
                g_buf1[o0 + 1] = scs_g(maxabs4(ya[2], ya[3], ya[6], ya[7]), e0);
                g_buf1[o1]     = scs_g(maxabs4(yb[0], yb[1], yb[4], yb[5]), e1);
                g_buf1[o1 + 1] = scs_g(maxabs4(yb[2], yb[3], yb[6], yb[7]), e1);
            }
        }
    }
    __syncthreads();   // g_buf1 visible block-wide; conv smem regions now dead

    // ===== phase 3: layer2 depthwise + pointwise + pool + g =====
    {
        float* s_t2d = sm;                           // 11520
        ull*   s_w2  = (ull*)(sm + 11520);           // 1600 ull
        float* s_xn  = sm + 11520 + 3200;            // 144
        float* s_e2p = s_xn + 144;                   // 40

        for (int i = tid; i < 1600; i += 392) s_w2[i] = g_wn2pp[i];
        if (tid < 40) s_e2p[tid] = g_e2p[tid];
        float qv2d = g_qv[1], qv2p = g_qv[2];

        // phase A: depthwise 3x3 + g -> smem (plain loads: same-block data)
        for (int tile = tid; tile < 1920; tile += 392) {
            int ch = tile / 24, rest = tile % 24;
            int oy = rest / 2, half = rest % 2;
            int ox0 = half * 6;
            const float* wp = g_wn2d + ch * 9;
            float wreg[9];
            #pragma unroll
            for (int k = 0; k < 9; k++) wreg[k] = wp[k];
            float e = g_e2d[ch];
            const float* xr = g_buf1 + (img * 80 + ch) * 196 + oy * 14 + ox0;
            float rw[3][8];
            #pragma unroll
            for (int rr = 0; rr < 3; rr++)
                #pragma unroll
                for (int j = 0; j < 8; j++) rw[rr][j] = xr[rr * 14 + j];
            float* op = s_t2d + ch * 144 + oy * 12 + ox0;
            #pragma unroll
            for (int ox = 0; ox < 6; ox++) {
                float num = 0.f, ss = 0.f;
                #pragma unroll
                for (int ky = 0; ky < 3; ky++)
                    #pragma unroll
                    for (int kx = 0; kx < 3; kx++) {
                        float v = rw[ky][ox + kx];
                        num = fmaf(wreg[ky * 3 + kx], v, num);
                        ss  = __fadd_rn(ss, __fmul_rn(v, v));
                    }
                float y = __fdiv_rn(num, __fadd_rn(sqrtf(__fadd_rn(ss, EPS)), qv2d));
                op[ox] = scs_g(y, e);
            }
        }
        __syncthreads();

        // phase B1: per-pixel channel-norm denominators (pixel pairs)
        if (tid < 72) {
            int pix0 = 2 * tid;
            float ssa = 0.f, ssb = 0.f;
            for (int k = 0; k < 80; k++) {
                float2 v = *(const float2*)&s_t2d[k * 144 + pix0];
                ssa = __fadd_rn(ssa, __fmul_rn(v.x, v.x));
                ssb = __fadd_rn(ssb, __fmul_rn(v.y, v.y));
            }
            s_xn[pix0]     = __fadd_rn(sqrtf(__fadd_rn(ssa, EPS)), qv2p);
            s_xn[pix0 + 1] = __fadd_rn(sqrtf(__fadd_rn(ssb, EPS)), qv2p);
        }
        __syncthreads();

        // phase B2: pointwise channel-pair FFMA2 + pool 2x2 + g
        if (tid < 360) {
            int cg = tid / 36, quad = tid % 36;
            int qy = quad / 6, qx = quad % 6;
            int p00 = (2 * qy) * 12 + 2 * qx;
            int p10 = p00 + 12;
            ull acc2[2][4];
            #pragma unroll
            for (int pr = 0; pr < 2; pr++)
                #pragma unroll
                for (int j = 0; j < 4; j++) acc2[pr][j] = 0ull;
            for (int k = 0; k < 80; k++) {
                float2 xa = *(const float2*)&s_t2d[k * 144 + p00];
                float2 xb = *(const float2*)&s_t2d[k * 144 + p10];
                ull xv0 = pack2(xa.x, xa.x), xv1 = pack2(xa.y, xa.y);
                ull xv2 = pack2(xb.x, xb.x), xv3 = pack2(xb.y, xb.y);
                #pragma unroll
                for (int pr = 0; pr < 2; pr++) {
                    ull w2 = s_w2[(cg * 2 + pr) * 80 + k];
                    acc2[pr][0] = ffma2(w2, xv0, acc2[pr][0]);
                    acc2[pr][1] = ffma2(w2, xv1, acc2[pr][1]);
                    acc2[pr][2] = ffma2(w2, xv2, acc2[pr][2]);
                    acc2[pr][3] = ffma2(w2, xv3, acc2[pr][3]);
                }
            }
            float n0 = s_xn[p00], n1 = s_xn[p00 + 1], n2 = s_xn[p10], n3 = s_xn[p10 + 1];
            #pragma unroll
            for (int pr = 0; pr < 2; pr++) {
                float a0, b0, a1, b1, a2, b2, a3, b3;
                unpack2(acc2[pr][0], a0, b0);
                unpack2(acc2[pr][1], a1, b1);
                unpack2(acc2[pr][2], a2, b2);
                unpack2(acc2[pr][3], a3, b3);
                float va = maxabs4(__fdiv_rn(a0, n0), __fdiv_rn(a1, n1),
                                   __fdiv_rn(a2, n2), __fdiv_rn(a3, n3));
                float vb = maxabs4(__fdiv_rn(b0, n0), __fdiv_rn(b1, n1),
                                   __fdiv_rn(b2, n2), __fdiv_rn(b3, n3));
                int co0 = cg * 4 + 2 * pr;
                int co1 = co0 + 1;
                g_buf2[((img * 40 + co0) * 6 + qy) * 6 + qx] = scs_g(va, s_e2p[co0]);
                g_buf2[((img * 40 + co1) * 6 + qy) * 6 + qx] = scs_g(vb, s_e2p[co1]);
            }
        }
    }
    __syncthreads();   // g_buf2 visible; k2 smem dead

    // ===== phase 4: layer3 conv 3x3 + pool 4x4 + g + FC =====
    {
        float* s_in   = sm;              // 1440
        float* s_w3   = sm + 1440;       // 14400
        float* s_wo   = s_w3 + 14400;    // 400
        float* s_e3   = s_wo + 400;      // 40
        float* s_xn   = s_e3 + 40;       // 16
        float* s_qmax = s_xn + 16;       // 160
        float* s_qmin = s_qmax + 160;    // 160
        float* s_vec  = s_qmin + 160;    // 40
        float* s_bo   = s_vec + 40;      // 16

        const float4* src = (const float4*)(g_buf2 + img * 1440);
        for (int i = tid; i < 360; i += 392) ((float4*)s_in)[i] = src[i];
        for (int i = tid; i < 3600; i += 392) ((float4*)s_w3)[i] = ((const float4*)g_wn3)[i];
        for (int i = tid; i < 400; i += 392) s_wo[i] = wo_g[i];
        if (tid < 40) s_e3[tid] = g_e3[tid];
        if (tid < 10) s_bo[tid] = bo_g[tid];
        __syncthreads();
        float qv3 = g_qv[3];

        if (tid < 16) {
            int oy = tid / 4, ox = tid % 4;
            float ss = 0.f;
            #pragma unroll
            for (int ky = 0; ky < 3; ky++)
                #pragma unroll
                for (int kx = 0; kx < 3; kx++)
                    for (int c = 0; c < 40; c++) {
                        float v = s_in[c * 36 + (oy + ky) * 6 + ox + kx];
                        ss = __fadd_rn(ss, __fmul_rn(v, v));
                    }
            s_xn[tid] = __fadd_rn(sqrtf(__fadd_rn(ss, EPS)), qv3);
        }
        __syncthreads();

        if (tid < 160) {   // conv with FFMA2 position pairs
            int co = tid >> 2, quad = tid & 3;
            int qy = quad >> 1, qx = quad & 1;
            ull accA = 0ull, accB = 0ull;
            #pragma unroll
            for (int ky = 0; ky < 3; ky++)
                #pragma unroll
                for (int kx = 0; kx < 3; kx++)
                    for (int c = 0; c < 40; c++) {
                        float w = s_w3[(co * 40 + c) * 9 + ky * 3 + kx];
                        ull w2 = pack2(w, w);
                        const float* ip = &s_in[c * 36];
                        float v0 = ip[(2 * qy + ky) * 6 + 2 * qx + kx];
                        float v1 = ip[(2 * qy + ky) * 6 + 2 * qx + 1 + kx];
                        float v2 = ip[(2 * qy + 1 + ky) * 6 + 2 * qx + kx];
                        float v3 = ip[(2 * qy + 1 + ky) * 6 + 2 * qx + 1 + kx];
                        accA = ffma2(w2, pack2(v0, v1), accA);
                        accB = ffma2(w2, pack2(v2, v3), accB);
                    }
            float a0, a1, a2, a3;
            unpack2(accA, a0, a1);
            unpack2(accB, a2, a3);
            float y0 = __fdiv_rn(a0, s_xn[(2 * qy) * 4 + 2 * qx]);
            float y1 = __fdiv_rn(a1, s_xn[(2 * qy) * 4 + 2 * qx + 1]);
            float y2 = __fdiv_rn(a2, s_xn[(2 * qy + 1) * 4 + 2 * qx]);
            float y3 = __fdiv_rn(a3, s_xn[(2 * qy + 1) * 4 + 2 * qx + 1]);
            s_qmax[tid] = fmaxf(fmaxf(y0, y1), fmaxf(y2, y3));
            s_qmin[tid] = fminf(fminf(y0, y1), fminf(y2, y3));
        }
        __syncthreads();
        if (tid < 40) {
            float pmx = fmaxf(fmaxf(s_qmax[tid * 4], s_qmax[tid * 4 + 1]),
                              fmaxf(s_qmax[tid * 4 + 2], s_qmax[tid * 4 + 3]));
            float pmn = fminf(fminf(s_qmin[tid * 4], s_qmin[tid * 4 + 1]),
                              fminf(s_qmin[tid * 4 + 2], s_qmin[tid * 4 + 3]));
            float v = (pmx >= -pmn) ? pmx : pmn;
            s_vec[tid] = scs_g(v, s_e3[tid]);
        }
        __syncthreads();
        if (tid < 10) {
            float s = 0.f;
            #pragma unroll 1
            for (int c = 0; c < 40; c++) s = fmaf(s_vec[c], s_wo[tid * 40 + c], s);
            out[img * 10 + tid] = __fadd_rn(s, s_bo[tid]);
        }
    }
}

// ---------------- launch ------------------------------------------------------
extern "C" void kernel_launch(void* const* d_in, const int* in_sizes, int n_in,
                              void* d_out, int out_size) {
    const float* x   = (const float*)d_in[0];
    const float* w1  = (const float*)d_in[1];
    const float* p1  = (const float*)d_in[2];
    const float* q1  = (const float*)d_in[3];
    const float* w2d = (const float*)d_in[4];
    const float* p2d = (const float*)d_in[5];
    const float* q2d = (const float*)d_in[6];
    const float* w2p = (const float*)d_in[7];
    const float* p2p = (const float*)d_in[8];
    const float* q2p = (const float*)d_in[9];
    const float* w3  = (const float*)d_in[10];
    const float* p3  = (const float*)d_in[11];
    const float* q3  = (const float*)d_in[12];
    const float* wo  = (const float*)d_in[13];
    const float* bo  = (const float*)d_in[14];
    float* out = (float*)d_out;

    int N = in_sizes[0] / 3072;

    static const size_t SMM = MEGA_SMEMF * sizeof(float);
    cudaFuncSetAttribute(mega_kernel, cudaFuncAttributeMaxDynamicSharedMemorySize, (int)SMM);

    prep_kernel<<<240, 32>>>(w1, p1, q1, w2d, p2d, q2d, w2p, p2p, q2p, w3, p3, q3);
    mega_kernel<<<N, 392, SMM>>>(x, wo, bo, out);
}

// round 15
// speedup vs baseline: 1.5096x; 1.0143x over previous
#include <cuda_runtime.h>
#include <math.h>

#define EPS 1e-12f
typedef unsigned long long ull;

// ---- packed f32x2 helpers (each half = separately-rounded IEEE op) ---------
__device__ __forceinline__ ull pack2(float lo, float hi) {
    ull r; asm("mov.b64 %0, {%1,%2};" : "=l"(r) : "f"(lo), "f"(hi)); return r;
}
__device__ __forceinline__ void unpack2(ull p, float& lo, float& hi) {
    asm("mov.b64 {%0,%1}, %2;" : "=f"(lo), "=f"(hi) : "l"(p));
}
__device__ __forceinline__ ull ffma2(ull a, ull b, ull c) {
    ull d; asm("fma.rn.f32x2 %0, %1, %2, %3;" : "=l"(d) : "l"(a), "l"(b), "l"(c));
    return d;
}

// ---------------- persistent scratch ----------------------------------------
__device__ ull    g_wn1p[40 * 75];    // conv1 weights, channel-pair packed
__device__ float  g_e1[80];
__device__ float  g_wn2d[80 * 9];
__device__ float  g_e2d[80];
__device__ ull    g_wn2pp[20 * 80];   // pointwise weights, channel-pair packed
__device__ float  g_e2p[40];
__device__ float  g_wn3[40 * 360];
__device__ float  g_e3[40];
__device__ float  g_qv[4];

__device__ float g_buf1[1024 * 80 * 14 * 14]; // pooled layer1 g-output
__device__ float g_buf2[1024 * 40 * 6 * 6];   // pooled layer2 g-output

// g(y) = sign(y) * (|y|+EPS)^e
__device__ __forceinline__ float scs_g(float y, float e) {
    float a = __fadd_rn(fabsf(y), EPS);
    float r = powf(a, e);
    return (y > 0.f) ? r : ((y < 0.f) ? -r : 0.f);
}

__device__ __forceinline__ float maxabs4(float a, float b, float c, float d) {
    float pmx = fmaxf(fmaxf(a, b), fmaxf(c, d));
    float pmn = fminf(fminf(a, b), fminf(c, d));
    return (pmx >= -pmn) ? pmx : pmn;
}

// ---------------- weight prep (chains bit-identical) ------------------------
__global__ void prep_kernel(const float* w1, const float* p1, const float* q1,
                            const float* w2d, const float* p2d, const float* q2d,
                            const float* w2p, const float* p2p, const float* q2p,
                            const float* w3, const float* p3, const float* q3) {
    int b = blockIdx.x, t = threadIdx.x;
    const float *w, *p, *q;
    float *wn, *e;
    int n, c, li;
    if (b < 80)       { c = b;       w = w1  + c * 75;  n = 75;  wn = 0;              p = p1;  q = q1;  e = g_e1;  li = 0; }
    else if (b < 160) { c = b - 80;  w = w2d + c * 9;   n = 9;   wn = g_wn2d + c * 9; p = p2d; q = q2d; e = g_e2d; li = 1; }
    else if (b < 200) { c = b - 160; w = w2p + c * 80;  n = 80;  wn = 0;              p = p2p; q = q2p; e = g_e2p; li = 2; }
    else              { c = b - 200; w = w3  + c * 360; n = 360; wn = g_wn3 + c * 360; p = p3; q = q3;  e = g_e3;  li = 3; }
    float qt = __fdiv_rn(q[0], 100.0f);
    float qv = __fmul_rn(qt, qt);
    float s = 0.f;
    for (int i = t; i < n; i += 32) {
        float v = w[i];
        s = __fadd_rn(s, __fmul_rn(v, v));
    }
    #pragma unroll
    for (int o = 16; o > 0; o >>= 1)
        s = __fadd_rn(s, __shfl_down_sync(0xffffffffu, s, o));
    s = __shfl_sync(0xffffffffu, s, 0);
    float wnorm = __fadd_rn(sqrtf(__fadd_rn(s, EPS)), qv);
    for (int i = t; i < n; i += 32) {
        float v = __fdiv_rn(w[i], wnorm);
        if (li == 0) {
            ((float*)g_wn1p)[(c >> 1) * 150 + 2 * i + (c & 1)] = v;
        } else if (li == 2) {
            ((float*)g_wn2pp)[(c >> 1) * 160 + 2 * i + (c & 1)] = v;
        } else {
            wn[i] = v;
        }
    }
    if (t == 0) {
        float pe = __fdiv_rn(p[c], 10.0f);
        e[c] = __fmul_rn(pe, pe);
        if (c == 0) g_qv[li] = qv;
    }
}

// ---------------- megakernel: one image per block, all layers ---------------
#define MEGA_SMEMF 16672
__global__ void __launch_bounds__(392, 3) mega_kernel(const float* x,
                                                      const float* wo_g, const float* bo_g,
                                                      float* out) {
    extern __shared__ float sm[];
    int img = blockIdx.x, tid = threadIdx.x;

    // ===== phase 0: load image + conv1 weights =====
    {
        float* sx = sm;
        ull*   sw2 = (ull*)(sm + 3072);
        float* se = sm + 3072 + 6000 + 784;
        const float* xp = x + img * 3072;
        for (int i = tid; i < 3072; i += 392) sx[i] = xp[i];
        for (int i = tid; i < 3000; i += 392) sw2[i] = g_wn1p[i];
        if (tid < 80) se[tid] = g_e1[tid];
    }
    __syncthreads();

    // ===== phase 1: layer1 patch norms ((ky,kx,c) chain) =====
    {
        float* sx = sm;
        float* sxn = sm + 3072 + 6000;
        float qv = g_qv[0];
        for (int pos = tid; pos < 784; pos += 392) {
            int oy = pos / 28, ox = pos % 28;
            float ss = 0.f;
            #pragma unroll
            for (int ky = 0; ky < 5; ky++)
                #pragma unroll
                for (int kx = 0; kx < 5; kx++)
                    #pragma unroll
                    for (int c = 0; c < 3; c++) {
                        float v = sx[c * 1024 + (oy + ky) * 32 + ox + kx];
                        ss = __fadd_rn(ss, __fmul_rn(v, v));
                    }
            sxn[pos] = __fadd_rn(sqrtf(__fadd_rn(ss, EPS)), qv);
        }
    }
    __syncthreads();

    // ===== phase 2: conv1 5x5 + pool + g (10 passes x 4 out-channels) =====
    // thread = (ct, pooled output); 4 conv positions, 2 channel-pairs/pass
    {
        float* sx = sm;
        ull*   sw2 = (ull*)(sm + 3072);
        float* sxn = sm + 3072 + 6000;
        float* se = sxn + 784;
        int ct = tid / 196;            // 0..1
        int pos = tid % 196;
        int py = pos / 14, px = pos % 14;
        int cx0 = 2 * px;

        float xnv[4];
        #pragma unroll
        for (int r = 0; r < 2; r++)
            #pragma unroll
            for (int cl = 0; cl < 2; cl++)
                xnv[r * 2 + cl] = sxn[(2 * py + r) * 28 + cx0 + cl];

        #pragma unroll 1
        for (int pass = 0; pass < 10; pass++) {
            ull acc2[2][4];
            #pragma unroll
            for (int a = 0; a < 2; a++)
                #pragma unroll
                for (int j = 0; j < 4; j++) acc2[a][j] = 0ull;

            #pragma unroll 1
            for (int c = 0; c < 3; c++) {
                const float* xbase = &sx[c * 1024 + (2 * py) * 32 + cx0];
                ull xdA[6], xdB[6];
                #pragma unroll
                for (int j = 0; j < 6; j++) { float v = xbase[j];      xdA[j] = pack2(v, v); }
                #pragma unroll
                for (int j = 0; j < 6; j++) { float v = xbase[32 + j]; xdB[j] = pack2(v, v); }
                #pragma unroll
                for (int ky = 0; ky < 5; ky++) {
                    #pragma unroll
                    for (int kx = 0; kx < 5; kx++) {
                        int widx = c * 25 + ky * 5 + kx;
                        #pragma unroll
                        for (int t2 = 0; t2 < 2; t2++) {
                            ull w2 = sw2[(pass * 4 + ct * 2 + t2) * 75 + widx];
                            acc2[t2][0] = ffma2(w2, xdA[kx],     acc2[t2][0]);
                            acc2[t2][1] = ffma2(w2, xdA[kx + 1], acc2[t2][1]);
                            acc2[t2][2] = ffma2(w2, xdB[kx],     acc2[t2][2]);
                            acc2[t2][3] = ffma2(w2, xdB[kx + 1], acc2[t2][3]);
                        }
                    }
                    if (ky < 4) {   // rotate rows (register renaming)
                        #pragma unroll
                        for (int j = 0; j < 6; j++) xdA[j] = xdB[j];
                        #pragma unroll
                        for (int j = 0; j < 6; j++) {
                            float v = xbase[(ky + 2) * 32 + j];
                            xdB[j] = pack2(v, v);
                        }
                    }
                }
            }

            #pragma unroll
            for (int t2 = 0; t2 < 2; t2++) {
                float ya[4], yb[4];
                #pragma unroll
                for (int j = 0; j < 4; j++) unpack2(acc2[t2][j], ya[j], yb[j]);
                #pragma unroll
                for (int j = 0; j < 4; j++) {
                    ya[j] = __fdiv_rn(ya[j], xnv[j]);
                    yb[j] = __fdiv_rn(yb[j], xnv[j]);
                }
                int co = (pass * 4 + ct * 2 + t2) * 2;
                float e0 = se[co];
                float e1 = se[co + 1];
                int o0 = ((img * 80 + co) * 14 + py) * 14 + px;
                int o1 = o0 + 196;
                g_buf1[o0] = scs_g(maxabs4(ya[0], ya[1], ya[2], ya[3]), e0);
                g_buf1[o1] = scs_g(maxabs4(yb[0], yb[1], yb[2], yb[3]), e1);
            }
        }
    }
    __syncthreads();   // g_buf1 visible block-wide; conv smem regions now dead

    // ===== phase 3: layer2 depthwise + pointwise + pool + g =====
    {
        float* s_t2d = sm;                           // 11520
        ull*   s_w2  = (ull*)(sm + 11520);           // 1600 ull
        float* s_xn  = sm + 11520 + 3200;            // 144
        float* s_e2p = s_xn + 144;                   // 40

        for (int i = tid; i < 1600; i += 392) s_w2[i] = g_wn2pp[i];
        if (tid < 40) s_e2p[tid] = g_e2p[tid];
        float qv2d = g_qv[1], qv2p = g_qv[2];

        // phase A: depthwise 3x3 + g -> smem (plain loads: same-block data)
        for (int tile = tid; tile < 1920; tile += 392) {
            int ch = tile / 24, rest = tile % 24;
            int oy = rest / 2, half = rest % 2;
            int ox0 = half * 6;
            const float* wp = g_wn2d + ch * 9;
            float wreg[9];
            #pragma unroll
            for (int k = 0; k < 9; k++) wreg[k] = wp[k];
            float e = g_e2d[ch];
            const float* xr = g_buf1 + (img * 80 + ch) * 196 + oy * 14 + ox0;
            float rw[3][8];
            #pragma unroll
            for (int rr = 0; rr < 3; rr++)
                #pragma unroll
                for (int j = 0; j < 8; j++) rw[rr][j] = xr[rr * 14 + j];
            float* op = s_t2d + ch * 144 + oy * 12 + ox0;
            #pragma unroll
            for (int ox = 0; ox < 6; ox++) {
                float num = 0.f, ss = 0.f;
                #pragma unroll
                for (int ky = 0; ky < 3; ky++)
                    #pragma unroll
                    for (int kx = 0; kx < 3; kx++) {
                        float v = rw[ky][ox + kx];
                        num = fmaf(wreg[ky * 3 + kx], v, num);
                        ss  = __fadd_rn(ss, __fmul_rn(v, v));
                    }
                float y = __fdiv_rn(num, __fadd_rn(sqrtf(__fadd_rn(ss, EPS)), qv2d));
                op[ox] = scs_g(y, e);
            }
        }
        __syncthreads();

        // phase B1: per-pixel channel-norm denominators (pixel pairs)
        if (tid < 72) {
            int pix0 = 2 * tid;
            float ssa = 0.f, ssb = 0.f;
            for (int k = 0; k < 80; k++) {
                float2 v = *(const float2*)&s_t2d[k * 144 + pix0];
                ssa = __fadd_rn(ssa, __fmul_rn(v.x, v.x));
                ssb = __fadd_rn(ssb, __fmul_rn(v.y, v.y));
            }
            s_xn[pix0]     = __fadd_rn(sqrtf(__fadd_rn(ssa, EPS)), qv2p);
            s_xn[pix0 + 1] = __fadd_rn(sqrtf(__fadd_rn(ssb, EPS)), qv2p);
        }
        __syncthreads();

        // phase B2: pointwise channel-pair FFMA2 + pool 2x2 + g
        if (tid < 360) {
            int cg = tid / 36, quad = tid % 36;
            int qy = quad / 6, qx = quad % 6;
            int p00 = (2 * qy) * 12 + 2 * qx;
            int p10 = p00 + 12;
            ull acc2[2][4];
            #pragma unroll
            for (int pr = 0; pr < 2; pr++)
                #pragma unroll
                for (int j = 0; j < 4; j++) acc2[pr][j] = 0ull;
            for (int k = 0; k < 80; k++) {
                float2 xa = *(const float2*)&s_t2d[k * 144 + p00];
                float2 xb = *(const float2*)&s_t2d[k * 144 + p10];
                ull xv0 = pack2(xa.x, xa.x), xv1 = pack2(xa.y, xa.y);
                ull xv2 = pack2(xb.x, xb.x), xv3 = pack2(xb.y, xb.y);
                #pragma unroll
                for (int pr = 0; pr < 2; pr++) {
                    ull w2 = s_w2[(cg * 2 + pr) * 80 + k];
                    acc2[pr][0] = ffma2(w2, xv0, acc2[pr][0]);
                    acc2[pr][1] = ffma2(w2, xv1, acc2[pr][1]);
                    acc2[pr][2] = ffma2(w2, xv2, acc2[pr][2]);
                    acc2[pr][3] = ffma2(w2, xv3, acc2[pr][3]);
                }
            }
            float n0 = s_xn[p00], n1 = s_xn[p00 + 1], n2 = s_xn[p10], n3 = s_xn[p10 + 1];
            #pragma unroll
            for (int pr = 0; pr < 2; pr++) {
                float a0, b0, a1, b1, a2, b2, a3, b3;
                unpack2(acc2[pr][0], a0, b0);
                unpack2(acc2[pr][1], a1, b1);
                unpack2(acc2[pr][2], a2, b2);
                unpack2(acc2[pr][3], a3, b3);
                float va = maxabs4(__fdiv_rn(a0, n0), __fdiv_rn(a1, n1),
                                   __fdiv_rn(a2, n2), __fdiv_rn(a3, n3));
                float vb = maxabs4(__fdiv_rn(b0, n0), __fdiv_rn(b1, n1),
                                   __fdiv_rn(b2, n2), __fdiv_rn(b3, n3));
                int co0 = cg * 4 + 2 * pr;
                int co1 = co0 + 1;
                g_buf2[((img * 40 + co0) * 6 + qy) * 6 + qx] = scs_g(va, s_e2p[co0]);
                g_buf2[((img * 40 + co1) * 6 + qy) * 6 + qx] = scs_g(vb, s_e2p[co1]);
            }
        }
    }
    __syncthreads();   // g_buf2 visible; k2 smem dead

    // ===== phase 4: layer3 conv 3x3 + pool 4x4 + g + FC =====
    {
        float* s_in   = sm;              // 1440
        float* s_w3   = sm + 1440;       // 14400
        float* s_wo   = s_w3 + 14400;    // 400
        float* s_e3   = s_wo + 400;      // 40
        float* s_xn   = s_e3 + 40;       // 16
        float* s_qmax = s_xn + 16;       // 160
        float* s_qmin = s_qmax + 160;    // 160
        float* s_vec  = s_qmin + 160;    // 40
        float* s_bo   = s_vec + 40;      // 16

        const float4* src = (const float4*)(g_buf2 + img * 1440);
        for (int i = tid; i < 360; i += 392) ((float4*)s_in)[i] = src[i];
        for (int i = tid; i < 3600; i += 392) ((float4*)s_w3)[i] = ((const float4*)g_wn3)[i];
        for (int i = tid; i < 400; i += 392) s_wo[i] = wo_g[i];
        if (tid < 40) s_e3[tid] = g_e3[tid];
        if (tid < 10) s_bo[tid] = bo_g[tid];
        __syncthreads();
        float qv3 = g_qv[3];

        if (tid < 16) {
            int oy = tid / 4, ox = tid % 4;
            float ss = 0.f;
            #pragma unroll
            for (int ky = 0; ky < 3; ky++)
                #pragma unroll
                for (int kx = 0; kx < 3; kx++)
                    for (int c = 0; c < 40; c++) {
                        float v = s_in[c * 36 + (oy + ky) * 6 + ox + kx];
                        ss = __fadd_rn(ss, __fmul_rn(v, v));
                    }
            s_xn[tid] = __fadd_rn(sqrtf(__fadd_rn(ss, EPS)), qv3);
        }
        __syncthreads();

        if (tid < 160) {   // conv with FFMA2 position pairs
            int co = tid >> 2, quad = tid & 3;
            int qy = quad >> 1, qx = quad & 1;
            ull accA = 0ull, accB = 0ull;
            #pragma unroll
            for (int ky = 0; ky < 3; ky++)
                #pragma unroll
                for (int kx = 0; kx < 3; kx++)
                    for (int c = 0; c < 40; c++) {
                        float w = s_w3[(co * 40 + c) * 9 + ky * 3 + kx];
                        ull w2 = pack2(w, w);
                        const float* ip = &s_in[c * 36];
                        float v0 = ip[(2 * qy + ky) * 6 + 2 * qx + kx];
                        float v1 = ip[(2 * qy + ky) * 6 + 2 * qx + 1 + kx];
                        float v2 = ip[(2 * qy + 1 + ky) * 6 + 2 * qx + kx];
                        float v3 = ip[(2 * qy + 1 + ky) * 6 + 2 * qx + 1 + kx];
                        accA = ffma2(w2, pack2(v0, v1), accA);
                        accB = ffma2(w2, pack2(v2, v3), accB);
                    }
            float a0, a1, a2, a3;
            unpack2(accA, a0, a1);
            unpack2(accB, a2, a3);
            float y0 = __fdiv_rn(a0, s_xn[(2 * qy) * 4 + 2 * qx]);
            float y1 = __fdiv_rn(a1, s_xn[(2 * qy) * 4 + 2 * qx + 1]);
            float y2 = __fdiv_rn(a2, s_xn[(2 * qy + 1) * 4 + 2 * qx]);
            float y3 = __fdiv_rn(a3, s_xn[(2 * qy + 1) * 4 + 2 * qx + 1]);
            s_qmax[tid] = fmaxf(fmaxf(y0, y1), fmaxf(y2, y3));
            s_qmin[tid] = fminf(fminf(y0, y1), fminf(y2, y3));
        }
        __syncthreads();
        if (tid < 40) {
            float pmx = fmaxf(fmaxf(s_qmax[tid * 4], s_qmax[tid * 4 + 1]),
                              fmaxf(s_qmax[tid * 4 + 2], s_qmax[tid * 4 + 3]));
            float pmn = fminf(fminf(s_qmin[tid * 4], s_qmin[tid * 4 + 1]),
                              fminf(s_qmin[tid * 4 + 2], s_qmin[tid * 4 + 3]));
            float v = (pmx >= -pmn) ? pmx : pmn;
            s_vec[tid] = scs_g(v, s_e3[tid]);
        }
        __syncthreads();
        if (tid < 10) {
            float s = 0.f;
            #pragma unroll 1
            for (int c = 0; c < 40; c++) s = fmaf(s_vec[c], s_wo[tid * 40 + c], s);
            out[img * 10 + tid] = __fadd_rn(s, s_bo[tid]);
        }
    }
}

// ---------------- launch ------------------------------------------------------
extern "C" void kernel_launch(void* const* d_in, const int* in_sizes, int n_in,
                              void* d_out, int out_size) {
    const float* x   = (const float*)d_in[0];
    const float* w1  = (const float*)d_in[1];
    const float* p1  = (const float*)d_in[2];
    const float* q1  = (const float*)d_in[3];
    const float* w2d = (const float*)d_in[4];
    const float* p2d = (const float*)d_in[5];
    const float* q2d = (const float*)d_in[6];
    const float* w2p = (const float*)d_in[7];
    const float* p2p = (const float*)d_in[8];
    const float* q2p = (const float*)d_in[9];
    const float* w3  = (const float*)d_in[10];
    const float* p3  = (const float*)d_in[11];
    const float* q3  = (const float*)d_in[12];
    const float* wo  = (const float*)d_in[13];
    const float* bo  = (const float*)d_in[14];
    float* out = (float*)d_out;

    int N = in_sizes[0] / 3072;

    static const size_t SMM = MEGA_SMEMF * sizeof(float);
    cudaFuncSetAttribute(mega_kernel, cudaFuncAttributeMaxDynamicSharedMemorySize, (int)SMM);

    prep_kernel<<<240, 32>>>(w1, p1, q1, w2d, p2d, q2d, w2p, p2p, q2p, w3, p3, q3);
    mega_kernel<<<N, 392, SMM>>>(x, wo, bo, out);
}

// round 16
// speedup vs baseline: 1.5294x; 1.0132x over previous
#include <cuda_runtime.h>
#include <math.h>

#define EPS 1e-12f
typedef unsigned long long ull;

// ---- packed f32x2 helpers (each half = separately-rounded IEEE op) ---------
__device__ __forceinline__ ull pack2(float lo, float hi) {
    ull r; asm("mov.b64 %0, {%1,%2};" : "=l"(r) : "f"(lo), "f"(hi)); return r;
}
__device__ __forceinline__ void unpack2(ull p, float& lo, float& hi) {
    asm("mov.b64 {%0,%1}, %2;" : "=f"(lo), "=f"(hi) : "l"(p));
}
__device__ __forceinline__ ull ffma2(ull a, ull b, ull c) {
    ull d; asm("fma.rn.f32x2 %0, %1, %2, %3;" : "=l"(d) : "l"(a), "l"(b), "l"(c));
    return d;
}

// ---------------- persistent scratch ----------------------------------------
// conv1 weights: [g][widx][t2] interleaved channel-pairs (g=0..19, t2=0..1)
__device__ ull    g_wn1q[20 * 75 * 2];
__device__ float  g_e1[80];
__device__ float  g_wn2d[80 * 9];
__device__ float  g_e2d[80];
// pointwise weights: [cg][k][pr] interleaved channel-pairs (cg=0..9, pr=0..1)
__device__ ull    g_wn2pq[10 * 80 * 2];
__device__ float  g_e2p[40];
__device__ float  g_wn3[40 * 360];
__device__ float  g_e3[40];
__device__ float  g_qv[4];

__device__ float g_buf1[1024 * 80 * 14 * 14]; // pooled layer1 g-output
__device__ float g_buf2[1024 * 40 * 6 * 6];   // pooled layer2 g-output

// g(y) = sign(y) * (|y|+EPS)^e
__device__ __forceinline__ float scs_g(float y, float e) {
    float a = __fadd_rn(fabsf(y), EPS);
    float r = powf(a, e);
    return (y > 0.f) ? r : ((y < 0.f) ? -r : 0.f);
}

__device__ __forceinline__ float maxabs4(float a, float b, float c, float d) {
    float pmx = fmaxf(fmaxf(a, b), fmaxf(c, d));
    float pmn = fminf(fminf(a, b), fminf(c, d));
    return (pmx >= -pmn) ? pmx : pmn;
}

// ---------------- weight prep (values & chains bit-identical) ---------------
__global__ void prep_kernel(const float* w1, const float* p1, const float* q1,
                            const float* w2d, const float* p2d, const float* q2d,
                            const float* w2p, const float* p2p, const float* q2p,
                            const float* w3, const float* p3, const float* q3) {
    int b = blockIdx.x, t = threadIdx.x;
    const float *w, *p, *q;
    float *wn, *e;
    int n, c, li;
    if (b < 80)       { c = b;       w = w1  + c * 75;  n = 75;  wn = 0;              p = p1;  q = q1;  e = g_e1;  li = 0; }
    else if (b < 160) { c = b - 80;  w = w2d + c * 9;   n = 9;   wn = g_wn2d + c * 9; p = p2d; q = q2d; e = g_e2d; li = 1; }
    else if (b < 200) { c = b - 160; w = w2p + c * 80;  n = 80;  wn = 0;              p = p2p; q = q2p; e = g_e2p; li = 2; }
    else              { c = b - 200; w = w3  + c * 360; n = 360; wn = g_wn3 + c * 360; p = p3; q = q3;  e = g_e3;  li = 3; }
    float qt = __fdiv_rn(q[0], 100.0f);
    float qv = __fmul_rn(qt, qt);
    float s = 0.f;
    for (int i = t; i < n; i += 32) {
        float v = w[i];
        s = __fadd_rn(s, __fmul_rn(v, v));
    }
    #pragma unroll
    for (int o = 16; o > 0; o >>= 1)
        s = __fadd_rn(s, __shfl_down_sync(0xffffffffu, s, o));
    s = __shfl_sync(0xffffffffu, s, 0);
    float wnorm = __fadd_rn(sqrtf(__fadd_rn(s, EPS)), qv);
    for (int i = t; i < n; i += 32) {
        float v = __fdiv_rn(w[i], wnorm);
        if (li == 0) {
            int pair = c >> 1, half = c & 1;
            int g = pair >> 1, t2 = pair & 1;
            ((float*)g_wn1q)[g * 300 + i * 4 + t2 * 2 + half] = v;
        } else if (li == 2) {
            int pair = c >> 1, half = c & 1;
            int cg = pair >> 1, pr = pair & 1;
            ((float*)g_wn2pq)[cg * 320 + i * 4 + pr * 2 + half] = v;
        } else {
            wn[i] = v;
        }
    }
    if (t == 0) {
        float pe = __fdiv_rn(p[c], 10.0f);
        e[c] = __fmul_rn(pe, pe);
        if (c == 0) g_qv[li] = qv;
    }
}

// ---------------- megakernel: one image per block, all layers ---------------
#define MEGA_SMEMF 16672
__global__ void __launch_bounds__(392, 3) mega_kernel(const float* x,
                                                      const float* wo_g, const float* bo_g,
                                                      float* out) {
    extern __shared__ float sm[];
    int img = blockIdx.x, tid = threadIdx.x;

    // ===== phase 0: load image + conv1 weights =====
    {
        float* sx = sm;
        ull*   sw2 = (ull*)(sm + 3072);
        float* se = sm + 3072 + 6000 + 784;
        const float* xp = x + img * 3072;
        for (int i = tid; i < 3072; i += 392) sx[i] = xp[i];
        for (int i = tid; i < 3000; i += 392) sw2[i] = g_wn1q[i];
        if (tid < 80) se[tid] = g_e1[tid];
    }
    __syncthreads();

    // ===== phase 1: layer1 patch norms ((ky,kx,c) chain) =====
    {
        float* sx = sm;
        float* sxn = sm + 3072 + 6000;
        float qv = g_qv[0];
        for (int pos = tid; pos < 784; pos += 392) {
            int oy = pos / 28, ox = pos % 28;
            float ss = 0.f;
            #pragma unroll
            for (int ky = 0; ky < 5; ky++)
                #pragma unroll
                for (int kx = 0; kx < 5; kx++)
                    #pragma unroll
                    for (int c = 0; c < 3; c++) {
                        float v = sx[c * 1024 + (oy + ky) * 32 + ox + kx];
                        ss = __fadd_rn(ss, __fmul_rn(v, v));
                    }
            sxn[pos] = __fadd_rn(sqrtf(__fadd_rn(ss, EPS)), qv);
        }
    }
    __syncthreads();

    // ===== phase 2: conv1 5x5 + pool + g (10 passes x 4 out-channels) =====
    // thread = (ct, pooled output); float2 window loads, LDS.128 weight pairs
    {
        float* sx = sm;
        ull*   sw2 = (ull*)(sm + 3072);
        float* sxn = sm + 3072 + 6000;
        float* se = sxn + 784;
        int ct = tid / 196;            // 0..1
        int pos = tid % 196;
        int py = pos / 14, px = pos % 14;
        int cx0 = 2 * px;

        float xnv[4];
        #pragma unroll
        for (int r = 0; r < 2; r++)
            #pragma unroll
            for (int cl = 0; cl < 2; cl++)
                xnv[r * 2 + cl] = sxn[(2 * py + r) * 28 + cx0 + cl];

        #pragma unroll 1
        for (int pass = 0; pass < 10; pass++) {
            int g = pass * 2 + ct;     // weight group 0..19
            const ull* wg = sw2 + g * 150;
            ull acc2[2][4];
            #pragma unroll
            for (int a = 0; a < 2; a++)
                #pragma unroll
                for (int j = 0; j < 4; j++) acc2[a][j] = 0ull;

            #pragma unroll 1
            for (int c = 0; c < 3; c++) {
                const float2* xb2 = (const float2*)&sx[c * 1024 + (2 * py) * 32 + cx0];
                ull xdA[6], xdB[6];
                #pragma unroll
                for (int j = 0; j < 3; j++) {
                    float2 u = xb2[j];
                    xdA[2 * j]     = pack2(u.x, u.x);
                    xdA[2 * j + 1] = pack2(u.y, u.y);
                }
                #pragma unroll
                for (int j = 0; j < 3; j++) {
                    float2 u = xb2[16 + j];
                    xdB[2 * j]     = pack2(u.x, u.x);
                    xdB[2 * j + 1] = pack2(u.y, u.y);
                }
                #pragma unroll
                for (int ky = 0; ky < 5; ky++) {
                    #pragma unroll
                    for (int kx = 0; kx < 5; kx++) {
                        int widx = c * 25 + ky * 5 + kx;
                        ulonglong2 w01 = *(const ulonglong2*)&wg[widx * 2];
                        acc2[0][0] = ffma2(w01.x, xdA[kx],     acc2[0][0]);
                        acc2[0][1] = ffma2(w01.x, xdA[kx + 1], acc2[0][1]);
                        acc2[0][2] = ffma2(w01.x, xdB[kx],     acc2[0][2]);
                        acc2[0][3] = ffma2(w01.x, xdB[kx + 1], acc2[0][3]);
                        acc2[1][0] = ffma2(w01.y, xdA[kx],     acc2[1][0]);
                        acc2[1][1] = ffma2(w01.y, xdA[kx + 1], acc2[1][1]);
                        acc2[1][2] = ffma2(w01.y, xdB[kx],     acc2[1][2]);
                        acc2[1][3] = ffma2(w01.y, xdB[kx + 1], acc2[1][3]);
                    }
                    if (ky < 4) {   // rotate rows (register renaming)
                        #pragma unroll
                        for (int j = 0; j < 6; j++) xdA[j] = xdB[j];
                        #pragma unroll
                        for (int j = 0; j < 3; j++) {
                            float2 u = xb2[(ky + 2) * 16 + j];
                            xdB[2 * j]     = pack2(u.x, u.x);
                            xdB[2 * j + 1] = pack2(u.y, u.y);
                        }
                    }
                }
            }

            #pragma unroll
            for (int t2 = 0; t2 < 2; t2++) {
                float ya[4], yb[4];
                #pragma unroll
                for (int j = 0; j < 4; j++) unpack2(acc2[t2][j], ya[j], yb[j]);
                #pragma unroll
                for (int j = 0; j < 4; j++) {
                    ya[j] = __fdiv_rn(ya[j], xnv[j]);
                    yb[j] = __fdiv_rn(yb[j], xnv[j]);
                }
                int co = (g * 2 + t2) * 2;
                float e0 = se[co];
                float e1 = se[co + 1];
                int o0 = ((img * 80 + co) * 14 + py) * 14 + px;
                int o1 = o0 + 196;
                g_buf1[o0] = scs_g(maxabs4(ya[0], ya[1], ya[2], ya[3]), e0);
                g_buf1[o1] = scs_g(maxabs4(yb[0], yb[1], yb[2], yb[3]), e1);
            }
        }
    }
    __syncthreads();   // g_buf1 visible block-wide; conv smem regions now dead

    // ===== phase 3: layer2 depthwise + pointwise + pool + g =====
    {
        float* s_t2d = sm;                           // 11520
        ull*   s_w2  = (ull*)(sm + 11520);           // 1600 ull [cg][k][pr]
        float* s_xn  = sm + 11520 + 3200;            // 144
        float* s_e2p = s_xn + 144;                   // 40

        for (int i = tid; i < 1600; i += 392) s_w2[i] = g_wn2pq[i];
        if (tid < 40) s_e2p[tid] = g_e2p[tid];
        float qv2d = g_qv[1], qv2p = g_qv[2];

        // phase A: depthwise 3x3 + g -> smem (plain loads: same-block data)
        for (int tile = tid; tile < 1920; tile += 392) {
            int ch = tile / 24, rest = tile % 24;
            int oy = rest / 2, half = rest % 2;
            int ox0 = half * 6;
            const float* wp = g_wn2d + ch * 9;
            float wreg[9];
            #pragma unroll
            for (int k = 0; k < 9; k++) wreg[k] = wp[k];
            float e = g_e2d[ch];
            const float* xr = g_buf1 + (img * 80 + ch) * 196 + oy * 14 + ox0;
            float rw[3][8];
            #pragma unroll
            for (int rr = 0; rr < 3; rr++)
                #pragma unroll
                for (int j = 0; j < 8; j++) rw[rr][j] = xr[rr * 14 + j];
            float* op = s_t2d + ch * 144 + oy * 12 + ox0;
            #pragma unroll
            for (int ox = 0; ox < 6; ox++) {
                float num = 0.f, ss = 0.f;
                #pragma unroll
                for (int ky = 0; ky < 3; ky++)
                    #pragma unroll
                    for (int kx = 0; kx < 3; kx++) {
                        float v = rw[ky][ox + kx];
                        num = fmaf(wreg[ky * 3 + kx], v, num);
                        ss  = __fadd_rn(ss, __fmul_rn(v, v));
                    }
                float y = __fdiv_rn(num, __fadd_rn(sqrtf(__fadd_rn(ss, EPS)), qv2d));
                op[ox] = scs_g(y, e);
            }
        }
        __syncthreads();

        // phase B1: per-pixel channel-norm denominators (pixel pairs)
        if (tid < 72) {
            int pix0 = 2 * tid;
            float ssa = 0.f, ssb = 0.f;
            for (int k = 0; k < 80; k++) {
                float2 v = *(const float2*)&s_t2d[k * 144 + pix0];
                ssa = __fadd_rn(ssa, __fmul_rn(v.x, v.x));
                ssb = __fadd_rn(ssb, __fmul_rn(v.y, v.y));
            }
            s_xn[pix0]     = __fadd_rn(sqrtf(__fadd_rn(ssa, EPS)), qv2p);
            s_xn[pix0 + 1] = __fadd_rn(sqrtf(__fadd_rn(ssb, EPS)), qv2p);
        }
        __syncthreads();

        // phase B2: pointwise channel-pair FFMA2 (LDS.128 weight pairs) + pool
        if (tid < 360) {
            int cg = tid / 36, quad = tid % 36;
            int qy = quad / 6, qx = quad % 6;
            int p00 = (2 * qy) * 12 + 2 * qx;
            int p10 = p00 + 12;
            ull acc2[2][4];
            #pragma unroll
            for (int pr = 0; pr < 2; pr++)
                #pragma unroll
                for (int j = 0; j < 4; j++) acc2[pr][j] = 0ull;
            const ull* wg = s_w2 + cg * 160;
            for (int k = 0; k < 80; k++) {
                float2 xa = *(const float2*)&s_t2d[k * 144 + p00];
                float2 xb = *(const float2*)&s_t2d[k * 144 + p10];
                ull xv0 = pack2(xa.x, xa.x), xv1 = pack2(xa.y, xa.y);
                ull xv2 = pack2(xb.x, xb.x), xv3 = pack2(xb.y, xb.y);
                ulonglong2 w01 = *(const ulonglong2*)&wg[k * 2];
                acc2[0][0] = ffma2(w01.x, xv0, acc2[0][0]);
                acc2[0][1] = ffma2(w01.x, xv1, acc2[0][1]);
                acc2[0][2] = ffma2(w01.x, xv2, acc2[0][2]);
                acc2[0][3] = ffma2(w01.x, xv3, acc2[0][3]);
                acc2[1][0] = ffma2(w01.y, xv0, acc2[1][0]);
                acc2[1][1] = ffma2(w01.y, xv1, acc2[1][1]);
                acc2[1][2] = ffma2(w01.y, xv2, acc2[1][2]);
                acc2[1][3] = ffma2(w01.y, xv3, acc2[1][3]);
            }
            float n0 = s_xn[p00], n1 = s_xn[p00 + 1], n2 = s_xn[p10], n3 = s_xn[p10 + 1];
            #pragma unroll
            for (int pr = 0; pr < 2; pr++) {
                float a0, b0, a1, b1, a2, b2, a3, b3;
                unpack2(acc2[pr][0], a0, b0);
                unpack2(acc2[pr][1], a1, b1);
                unpack2(acc2[pr][2], a2, b2);
                unpack2(acc2[pr][3], a3, b3);
                float va = maxabs4(__fdiv_rn(a0, n0), __fdiv_rn(a1, n1),
                                   __fdiv_rn(a2, n2), __fdiv_rn(a3, n3));
                float vb = maxabs4(__fdiv_rn(b0, n0), __fdiv_rn(b1, n1),
                                   __fdiv_rn(b2, n2), __fdiv_rn(b3, n3));
                int co0 = cg * 4 + 2 * pr;
                int co1 = co0 + 1;
                g_buf2[((img * 40 + co0) * 6 + qy) * 6 + qx] = scs_g(va, s_e2p[co0]);
                g_buf2[((img * 40 + co1) * 6 + qy) * 6 + qx] = scs_g(vb, s_e2p[co1]);
            }
        }
    }
    __syncthreads();   // g_buf2 visible; k2 smem dead

    // ===== phase 4: layer3 conv 3x3 + pool 4x4 + g + FC =====
    {
        float* s_in   = sm;              // 1440
        float* s_w3   = sm + 1440;       // 14400
        float* s_wo   = s_w3 + 14400;    // 400
        float* s_e3   = s_wo + 400;      // 40
        float* s_xn   = s_e3 + 40;       // 16
        float* s_qmax = s_xn + 16;       // 160
        float* s_qmin = s_qmax + 160;    // 160
        float* s_vec  = s_qmin + 160;    // 40
        float* s_bo   = s_vec + 40;      // 16

        const float4* src = (const float4*)(g_buf2 + img * 1440);
        for (int i = tid; i < 360; i += 392) ((float4*)s_in)[i] = src[i];
        for (int i = tid; i < 3600; i += 392) ((float4*)s_w3)[i] = ((const float4*)g_wn3)[i];
        for (int i = tid; i < 400; i += 392) s_wo[i] = wo_g[i];
        if (tid < 40) s_e3[tid] = g_e3[tid];
        if (tid < 10) s_bo[tid] = bo_g[tid];
        __syncthreads();
        float qv3 = g_qv[3];

        if (tid < 16) {
            int oy = tid / 4, ox = tid % 4;
            float ss = 0.f;
            #pragma unroll
            for (int ky = 0; ky < 3; ky++)
                #pragma unroll
                for (int kx = 0; kx < 3; kx++)
                    for (int c = 0; c < 40; c++) {
                        float v = s_in[c * 36 + (oy + ky) * 6 + ox + kx];
                        ss = __fadd_rn(ss, __fmul_rn(v, v));
                    }
            s_xn[tid] = __fadd_rn(sqrtf(__fadd_rn(ss, EPS)), qv3);
        }
        __syncthreads();

        if (tid < 160) {   // conv with FFMA2 position pairs
            int co = tid >> 2, quad = tid & 3;
            int qy = quad >> 1, qx = quad & 1;
            ull accA = 0ull, accB = 0ull;
            #pragma unroll
            for (int ky = 0; ky < 3; ky++)
                #pragma unroll
                for (int kx = 0; kx < 3; kx++)
                    for (int c = 0; c < 40; c++) {
                        float w = s_w3[(co * 40 + c) * 9 + ky * 3 + kx];
                        ull w2 = pack2(w, w);
                        const float* ip = &s_in[c * 36];
                        float v0 = ip[(2 * qy + ky) * 6 + 2 * qx + kx];
                        float v1 = ip[(2 * qy + ky) * 6 + 2 * qx + 1 + kx];
                        float v2 = ip[(2 * qy + 1 + ky) * 6 + 2 * qx + kx];
                        float v3 = ip[(2 * qy + 1 + ky) * 6 + 2 * qx + 1 + kx];
                        accA = ffma2(w2, pack2(v0, v1), accA);
                        accB = ffma2(w2, pack2(v2, v3), accB);
                    }
            float a0, a1, a2, a3;
            unpack2(accA, a0, a1);
            unpack2(accB, a2, a3);
            float y0 = __fdiv_rn(a0, s_xn[(2 * qy) * 4 + 2 * qx]);
            float y1 = __fdiv_rn(a1, s_xn[(2 * qy) * 4 + 2 * qx + 1]);
            float y2 = __fdiv_rn(a2, s_xn[(2 * qy + 1) * 4 + 2 * qx]);
            float y3 = __fdiv_rn(a3, s_xn[(2 * qy + 1) * 4 + 2 * qx + 1]);
            s_qmax[tid] = fmaxf(fmaxf(y0, y1), fmaxf(y2, y3));
            s_qmin[tid] = fminf(fminf(y0, y1), fminf(y2, y3));
        }
        __syncthreads();
        if (tid < 40) {
            float pmx = fmaxf(fmaxf(s_qmax[tid * 4], s_qmax[tid * 4 + 1]),
                              fmaxf(s_qmax[tid * 4 + 2], s_qmax[tid * 4 + 3]));
            float pmn = fminf(fminf(s_qmin[tid * 4], s_qmin[tid * 4 + 1]),
                              fminf(s_qmin[tid * 4 + 2], s_qmin[tid * 4 + 3]));
            float v = (pmx >= -pmn) ? pmx : pmn;
            s_vec[tid] = scs_g(v, s_e3[tid]);
        }
        __syncthreads();
        if (tid < 10) {
            float s = 0.f;
            #pragma unroll 1
            for (int c = 0; c < 40; c++) s = fmaf(s_vec[c], s_wo[tid * 40 + c], s);
            out[img * 10 + tid] = __fadd_rn(s, s_bo[tid]);
        }
    }
}

// ---------------- launch ------------------------------------------------------
extern "C" void kernel_launch(void* const* d_in, const int* in_sizes, int n_in,
                              void* d_out, int out_size) {
    const float* x   = (const float*)d_in[0];
    const float* w1  = (const float*)d_in[1];
    const float* p1  = (const float*)d_in[2];
    const float* q1  = (const float*)d_in[3];
    const float* w2d = (const float*)d_in[4];
    const float* p2d = (const float*)d_in[5];
    const float* q2d = (const float*)d_in[6];
    const float* w2p = (const float*)d_in[7];
    const float* p2p = (const float*)d_in[8];
    const float* q2p = (const float*)d_in[9];
    const float* w3  = (const float*)d_in[10];
    const float* p3  = (const float*)d_in[11];
    const float* q3  = (const float*)d_in[12];
    const float* wo  = (const float*)d_in[13];
    const float* bo  = (const float*)d_in[14];
    float* out = (float*)d_out;

    int N = in_sizes[0] / 3072;

    static const size_t SMM = MEGA_SMEMF * sizeof(float);
    cudaFuncSetAttribute(mega_kernel, cudaFuncAttributeMaxDynamicSharedMemorySize, (int)SMM);

    prep_kernel<<<240, 32>>>(w1, p1, q1, w2d, p2d, q2d, w2p, p2p, q2p, w3, p3, q3);
    mega_kernel<<<N, 392, SMM>>>(x, wo, bo, out);
}